// round 2
// baseline (speedup 1.0000x reference)
#include <cuda_runtime.h>
#include <cuda_bf16.h>
#include <cstdint>

// Problem constants
#define B_   2
#define L_   2048
#define Q_   4096
#define D_   512
#define H_   8
#define HD_  64

// ---------------------------------------------------------------------------
// Scratch (allocation-free: __device__ globals)
// ---------------------------------------------------------------------------
__device__ float g_xq[B_ * L_ * D_];   // x @ Wq^T + bq   (pre-upsample)
__device__ float g_k [B_ * L_ * D_];
__device__ float g_v [B_ * L_ * D_];
__device__ float g_q [B_ * Q_ * D_];   // upsampled q
__device__ float g_ao[B_ * Q_ * D_];   // attention output

// ---------------------------------------------------------------------------
// GEMM: C[m][n] = sum_k A[m][k] * W[n][k] + bias[n]
// Tiles 128x128x16, 256 threads, 8x8 microtile (cols split tx*4 / tx*4+64).
// grid.z selects one of up to 3 (W, bias, C) sets (fused QKV).
// ---------------------------------------------------------------------------
#define GBM 128
#define GBN 128
#define GBK 16

__global__ void __launch_bounds__(256) gemm_bias_kernel(
    const float* __restrict__ A, int M, int K,
    const float* __restrict__ W0, const float* __restrict__ b0, float* __restrict__ C0,
    const float* __restrict__ W1, const float* __restrict__ b1, float* __restrict__ C1,
    const float* __restrict__ W2, const float* __restrict__ b2, float* __restrict__ C2,
    int N)
{
    const float* W = W0; const float* bias = b0; float* C = C0;
    if (blockIdx.z == 1) { W = W1; bias = b1; C = C1; }
    else if (blockIdx.z == 2) { W = W2; bias = b2; C = C2; }

    __shared__ __align__(16) float As[GBK][GBM + 4];
    __shared__ __align__(16) float Ws[GBK][GBN + 4];

    const int t  = threadIdx.x;
    const int tx = t & 15;
    const int ty = t >> 4;
    const int m0 = blockIdx.y * GBM;
    const int n0 = blockIdx.x * GBN;

    const float* Ap = A + (size_t)m0 * K;
    const float* Wp = W + (size_t)n0 * K;

    float acc[8][8];
#pragma unroll
    for (int i = 0; i < 8; i++)
#pragma unroll
        for (int j = 0; j < 8; j++) acc[i][j] = 0.0f;

    for (int k0 = 0; k0 < K; k0 += GBK) {
#pragma unroll
        for (int c = 0; c < 2; c++) {
            int f   = c * 256 + t;
            int row = f >> 2;
            int c4  = f & 3;
            float4 av = *(const float4*)(Ap + (size_t)row * K + k0 + c4 * 4);
            As[c4 * 4 + 0][row] = av.x;
            As[c4 * 4 + 1][row] = av.y;
            As[c4 * 4 + 2][row] = av.z;
            As[c4 * 4 + 3][row] = av.w;
            float4 wv = *(const float4*)(Wp + (size_t)row * K + k0 + c4 * 4);
            Ws[c4 * 4 + 0][row] = wv.x;
            Ws[c4 * 4 + 1][row] = wv.y;
            Ws[c4 * 4 + 2][row] = wv.z;
            Ws[c4 * 4 + 3][row] = wv.w;
        }
        __syncthreads();

#pragma unroll
        for (int kk = 0; kk < GBK; kk++) {
            float a[8], bb[8];
            *(float4*)&a[0]  = *(const float4*)&As[kk][ty * 8];
            *(float4*)&a[4]  = *(const float4*)&As[kk][ty * 8 + 4];
            *(float4*)&bb[0] = *(const float4*)&Ws[kk][tx * 4];
            *(float4*)&bb[4] = *(const float4*)&Ws[kk][tx * 4 + 64];
#pragma unroll
            for (int i = 0; i < 8; i++)
#pragma unroll
                for (int j = 0; j < 8; j++)
                    acc[i][j] = fmaf(a[i], bb[j], acc[i][j]);
        }
        __syncthreads();
    }

    float4 bias0 = *(const float4*)(bias + n0 + tx * 4);
    float4 bias1 = *(const float4*)(bias + n0 + 64 + tx * 4);
#pragma unroll
    for (int i = 0; i < 8; i++) {
        size_t row = (size_t)(m0 + ty * 8 + i);
        float4 r0, r1;
        r0.x = acc[i][0] + bias0.x; r0.y = acc[i][1] + bias0.y;
        r0.z = acc[i][2] + bias0.z; r0.w = acc[i][3] + bias0.w;
        r1.x = acc[i][4] + bias1.x; r1.y = acc[i][5] + bias1.y;
        r1.z = acc[i][6] + bias1.z; r1.w = acc[i][7] + bias1.w;
        *(float4*)(C + row * N + n0 + tx * 4)      = r0;
        *(float4*)(C + row * N + n0 + 64 + tx * 4) = r1;
    }
}

// ---------------------------------------------------------------------------
// Upsample (linear, align_corners=False, factor 2): g_xq [B,L,D] -> g_q [B,Q,D]
// interp commutes with the linear projection, so bias already included.
// ---------------------------------------------------------------------------
__global__ void __launch_bounds__(256) upsample_kernel(
    const float* __restrict__ xq, float* __restrict__ qout)
{
    int idx = blockIdx.x * blockDim.x + threadIdx.x;   // float4 index, 2^20 total
    int d4 = idx & 127;            // D/4 = 128
    int i  = (idx >> 7) & 4095;    // Q = 4096
    int b  = idx >> 19;

    const float4* xb = (const float4*)xq + (size_t)b * L_ * 128;
    float4 r;
    if (i == 0) {
        r = xb[d4];
    } else {
        float src = (i - 0.5f) * 0.5f;
        int i0 = (int)src;
        float w = src - (float)i0;
        int i1 = min(i0 + 1, L_ - 1);
        float4 a = xb[(size_t)i0 * 128 + d4];
        float4 c = xb[(size_t)i1 * 128 + d4];
        r.x = a.x + (c.x - a.x) * w;
        r.y = a.y + (c.y - a.y) * w;
        r.z = a.z + (c.z - a.z) * w;
        r.w = a.w + (c.w - a.w) * w;
    }
    ((float4*)qout)[idx] = r;
}

// ---------------------------------------------------------------------------
// Flash attention, fp32. Grid (Q/64, H, B), 256 threads.
// Tiles: 64(q) x 64(k), hd=64. Thread (tx,ty)=16x16 owns 4x4 of S
// (rows ty*4+i, cols tx+j*16) and 4x4 of O (rows ty*4+i, dims tx*4+j).
// Only the k0==q0 tile needs masking. Scale = D^-0.5 folded into Q load.
// ---------------------------------------------------------------------------
#define AQ 64
#define AK 64
#define QPAD 68   // padded row stride for Qs/Ks/Ps

__global__ void __launch_bounds__(256) attn_kernel(
    const float* __restrict__ q, const float* __restrict__ k,
    const float* __restrict__ v, float* __restrict__ out)
{
    extern __shared__ float sm[];
    float (*Qs)[QPAD] = (float(*)[QPAD])sm;
    float (*Ks)[QPAD] = (float(*)[QPAD])(sm + AQ * QPAD);
    float (*Vs)[HD_]  = (float(*)[HD_]) (sm + 2 * AQ * QPAD);
    float (*Ps)[QPAD] = (float(*)[QPAD])(sm + 2 * AQ * QPAD + AK * HD_);

    const int t  = threadIdx.x;
    const int tx = t & 15;
    const int ty = t >> 4;
    const int q0 = blockIdx.x * AQ;
    const int h  = blockIdx.y;
    const int b  = blockIdx.z;

    const float scale = 0.04419417382415922f;  // 512^-0.5

    const float* qb = q + (size_t)b * Q_ * D_ + h * HD_;
    const float* kb = k + (size_t)b * L_ * D_ + h * HD_;
    const float* vb = v + (size_t)b * L_ * D_ + h * HD_;

    // Load + pre-scale Q tile (64 rows x 64 dims)
#pragma unroll
    for (int c = 0; c < 4; c++) {
        int f   = c * 256 + t;
        int row = f >> 4;
        int d4  = f & 15;
        float4 qv = *(const float4*)(qb + (size_t)(q0 + row) * D_ + d4 * 4);
        qv.x *= scale; qv.y *= scale; qv.z *= scale; qv.w *= scale;
        *(float4*)&Qs[row][d4 * 4] = qv;
    }

    float m[4], l[4], o[4][4];
#pragma unroll
    for (int i = 0; i < 4; i++) {
        m[i] = -1e30f; l[i] = 0.0f;
#pragma unroll
        for (int j = 0; j < 4; j++) o[i][j] = 0.0f;
    }

    const int ntiles = min(q0 / AK + 1, L_ / AK);

    for (int tIdx = 0; tIdx < ntiles; tIdx++) {
        const int k0 = tIdx * AK;
        __syncthreads();   // previous iteration done reading Ks/Vs/Ps
#pragma unroll
        for (int c = 0; c < 4; c++) {
            int f   = c * 256 + t;
            int row = f >> 4;
            int d4  = f & 15;
            *(float4*)&Ks[row][d4 * 4] =
                *(const float4*)(kb + (size_t)(k0 + row) * D_ + d4 * 4);
            *(float4*)&Vs[row][d4 * 4] =
                *(const float4*)(vb + (size_t)(k0 + row) * D_ + d4 * 4);
        }
        __syncthreads();

        // S = Qs @ Ks^T  (rows ty*4+i, cols tx+j*16)
        float s[4][4];
#pragma unroll
        for (int i = 0; i < 4; i++)
#pragma unroll
            for (int j = 0; j < 4; j++) s[i][j] = 0.0f;

#pragma unroll
        for (int d4 = 0; d4 < 16; d4++) {
            float4 qv[4], kv[4];
#pragma unroll
            for (int i = 0; i < 4; i++)
                qv[i] = *(const float4*)&Qs[ty * 4 + i][d4 * 4];
#pragma unroll
            for (int j = 0; j < 4; j++)
                kv[j] = *(const float4*)&Ks[tx + j * 16][d4 * 4];
#pragma unroll
            for (int i = 0; i < 4; i++)
#pragma unroll
                for (int j = 0; j < 4; j++) {
                    s[i][j] = fmaf(qv[i].x, kv[j].x, s[i][j]);
                    s[i][j] = fmaf(qv[i].y, kv[j].y, s[i][j]);
                    s[i][j] = fmaf(qv[i].z, kv[j].z, s[i][j]);
                    s[i][j] = fmaf(qv[i].w, kv[j].w, s[i][j]);
                }
        }

        // Causal mask (only the diagonal tile)
        if (k0 == q0) {
#pragma unroll
            for (int i = 0; i < 4; i++)
#pragma unroll
                for (int j = 0; j < 4; j++)
                    if (tx + j * 16 > ty * 4 + i) s[i][j] = -1e30f;
        }

        // Online softmax update (row stats replicated across the 16 tx lanes)
#pragma unroll
        for (int i = 0; i < 4; i++) {
            float mt = fmaxf(fmaxf(s[i][0], s[i][1]), fmaxf(s[i][2], s[i][3]));
            mt = fmaxf(mt, __shfl_xor_sync(0xffffffffu, mt, 8));
            mt = fmaxf(mt, __shfl_xor_sync(0xffffffffu, mt, 4));
            mt = fmaxf(mt, __shfl_xor_sync(0xffffffffu, mt, 2));
            mt = fmaxf(mt, __shfl_xor_sync(0xffffffffu, mt, 1));
            float mnew = fmaxf(m[i], mt);
            float corr = __expf(m[i] - mnew);
            float sum = 0.0f;
#pragma unroll
            for (int j = 0; j < 4; j++) {
                float p = __expf(s[i][j] - mnew);
                s[i][j] = p;
                sum += p;
            }
            sum += __shfl_xor_sync(0xffffffffu, sum, 8);
            sum += __shfl_xor_sync(0xffffffffu, sum, 4);
            sum += __shfl_xor_sync(0xffffffffu, sum, 2);
            sum += __shfl_xor_sync(0xffffffffu, sum, 1);
            l[i] = l[i] * corr + sum;
            m[i] = mnew;
#pragma unroll
            for (int j = 0; j < 4; j++) o[i][j] *= corr;
        }

        // Stage P into smem for the O-accumulate GEMM
#pragma unroll
        for (int i = 0; i < 4; i++)
#pragma unroll
            for (int j = 0; j < 4; j++)
                Ps[ty * 4 + i][tx + j * 16] = s[i][j];
        __syncthreads();

        // O += P @ V   (rows ty*4+i, dims tx*4+j)
#pragma unroll 4
        for (int c = 0; c < AK; c++) {
            float4 vv = *(const float4*)&Vs[c][tx * 4];
            float p0 = Ps[ty * 4 + 0][c];
            float p1 = Ps[ty * 4 + 1][c];
            float p2 = Ps[ty * 4 + 2][c];
            float p3 = Ps[ty * 4 + 3][c];
            o[0][0] = fmaf(p0, vv.x, o[0][0]); o[0][1] = fmaf(p0, vv.y, o[0][1]);
            o[0][2] = fmaf(p0, vv.z, o[0][2]); o[0][3] = fmaf(p0, vv.w, o[0][3]);
            o[1][0] = fmaf(p1, vv.x, o[1][0]); o[1][1] = fmaf(p1, vv.y, o[1][1]);
            o[1][2] = fmaf(p1, vv.z, o[1][2]); o[1][3] = fmaf(p1, vv.w, o[1][3]);
            o[2][0] = fmaf(p2, vv.x, o[2][0]); o[2][1] = fmaf(p2, vv.y, o[2][1]);
            o[2][2] = fmaf(p2, vv.z, o[2][2]); o[2][3] = fmaf(p2, vv.w, o[2][3]);
            o[3][0] = fmaf(p3, vv.x, o[3][0]); o[3][1] = fmaf(p3, vv.y, o[3][1]);
            o[3][2] = fmaf(p3, vv.z, o[3][2]); o[3][3] = fmaf(p3, vv.w, o[3][3]);
        }
    }

    // Epilogue: normalize and write [b, q0+r, h*64 + d]
    float* ob = out + ((size_t)b * Q_ + q0) * D_ + h * HD_;
#pragma unroll
    for (int i = 0; i < 4; i++) {
        float inv = 1.0f / l[i];
        float4 r;
        r.x = o[i][0] * inv; r.y = o[i][1] * inv;
        r.z = o[i][2] * inv; r.w = o[i][3] * inv;
        *(float4*)(ob + (size_t)(ty * 4 + i) * D_ + tx * 4) = r;
    }
}

// ---------------------------------------------------------------------------
// Launch
// ---------------------------------------------------------------------------
static const int ATT_SMEM = (2 * AQ * QPAD + AK * HD_ + AQ * QPAD) * 4;  // 68608 B

extern "C" void kernel_launch(void* const* d_in, const int* in_sizes, int n_in,
                              void* d_out, int out_size)
{
    const float* x  = (const float*)d_in[0];
    const float* Wq = (const float*)d_in[1];
    const float* bq = (const float*)d_in[2];
    const float* Wk = (const float*)d_in[3];
    const float* bk = (const float*)d_in[4];
    const float* Wv = (const float*)d_in[5];
    const float* bv = (const float*)d_in[6];
    const float* Wo = (const float*)d_in[7];
    const float* bo = (const float*)d_in[8];
    float* out = (float*)d_out;

    float *xq, *kk, *vv, *qq, *ao;
    cudaGetSymbolAddress((void**)&xq, g_xq);
    cudaGetSymbolAddress((void**)&kk, g_k);
    cudaGetSymbolAddress((void**)&vv, g_v);
    cudaGetSymbolAddress((void**)&qq, g_q);
    cudaGetSymbolAddress((void**)&ao, g_ao);

    cudaFuncSetAttribute(attn_kernel,
                         cudaFuncAttributeMaxDynamicSharedMemorySize, ATT_SMEM);

    // Fused QKV projections: xq/k/v = x @ W^T + b   (M=4096)
    dim3 gqkv(D_ / GBN, (B_ * L_) / GBM, 3);
    gemm_bias_kernel<<<gqkv, 256>>>(x, B_ * L_, D_,
                                    Wq, bq, xq,
                                    Wk, bk, kk,
                                    Wv, bv, vv, D_);

    // Upsample xq -> q  (2^20 float4, 256 threads/block)
    upsample_kernel<<<(B_ * Q_ * D_ / 4) / 256, 256>>>(xq, qq);

    // Flash attention
    attn_kernel<<<dim3(Q_ / AQ, H_, B_), 256, ATT_SMEM>>>(qq, kk, vv, ao);

    // Output projection: out = ao @ Wo^T + bo   (M=8192)
    dim3 gout(D_ / GBN, (B_ * Q_) / GBM, 1);
    gemm_bias_kernel<<<gout, 256>>>(ao, B_ * Q_, D_,
                                    Wo, bo, out,
                                    Wo, bo, out,
                                    Wo, bo, out, D_);
}

// round 3
// speedup vs baseline: 2.4484x; 2.4484x over previous
#include <cuda_runtime.h>
#include <cstdint>

// Problem constants
#define B_   2
#define L_   2048
#define Q_   4096
#define D_   512
#define H_   8
#define HD_  64

// ---------------------------------------------------------------------------
// Scratch (allocation-free: __device__ globals)
// ---------------------------------------------------------------------------
__device__ float g_xq[B_ * L_ * D_];   // x @ Wq^T + bq   (pre-upsample)
__device__ float g_k [B_ * L_ * D_];
__device__ float g_v [B_ * L_ * D_];
__device__ float g_q [B_ * Q_ * D_];   // upsampled q
__device__ float g_ao[B_ * Q_ * D_];   // attention output

// ---------------------------------------------------------------------------
// tf32 helpers
// ---------------------------------------------------------------------------
__device__ __forceinline__ uint32_t f2tf(float f) {
    uint32_t u;
    asm("cvt.rna.tf32.f32 %0, %1;" : "=r"(u) : "f"(f));
    return u;
}

// D(16x8) += A(16x8,row) * B(8x8,col)   tf32 inputs, fp32 accum
__device__ __forceinline__ void mma8(float* c,
                                     uint32_t a0, uint32_t a1, uint32_t a2, uint32_t a3,
                                     uint32_t b0, uint32_t b1) {
    asm volatile(
        "mma.sync.aligned.m16n8k8.row.col.f32.tf32.tf32.f32 "
        "{%0,%1,%2,%3}, {%4,%5,%6,%7}, {%8,%9}, {%0,%1,%2,%3};"
        : "+f"(c[0]), "+f"(c[1]), "+f"(c[2]), "+f"(c[3])
        : "r"(a0), "r"(a1), "r"(a2), "r"(a3), "r"(b0), "r"(b1));
}

// ---------------------------------------------------------------------------
// tf32 GEMM: C[m][n] = sum_k A[m][k]*W[n][k] + bias[n].  K = N = 512 fixed.
// Block tile 128x128, k-chunk 32. 256 threads = 8 warps (2 m x 4 n),
// warp tile 64x32 => 4 m-tiles x 4 n-tiles of m16n8k8.
// Smem padded stride 36 -> fragment LDS bank = (4*group + tig), conflict-free.
// grid.z picks one of 3 (W,bias,C) triples (fused QKV).
// ---------------------------------------------------------------------------
#define GP 36

__global__ void __launch_bounds__(256) gemm_tf32_kernel(
    const float* __restrict__ A,
    const float* __restrict__ W0, const float* __restrict__ b0_, float* __restrict__ C0,
    const float* __restrict__ W1, const float* __restrict__ b1_, float* __restrict__ C1,
    const float* __restrict__ W2, const float* __restrict__ b2_, float* __restrict__ C2)
{
    const float* W = W0; const float* bias = b0_; float* C = C0;
    if (blockIdx.z == 1) { W = W1; bias = b1_; C = C1; }
    else if (blockIdx.z == 2) { W = W2; bias = b2_; C = C2; }

    __shared__ uint32_t As[128 * GP];
    __shared__ uint32_t Ws[128 * GP];

    const int t    = threadIdx.x;
    const int lane = t & 31;
    const int wid  = t >> 5;
    const int g    = lane >> 2;   // group (row within fragment)
    const int tig  = lane & 3;    // thread-in-group
    const int wm   = (wid & 1) * 64;   // warp m offset in tile
    const int wn   = (wid >> 1) * 32;  // warp n offset in tile

    const int m0 = blockIdx.y * 128;
    const int n0 = blockIdx.x * 128;

    float acc[4][4][4];
#pragma unroll
    for (int mt = 0; mt < 4; mt++)
#pragma unroll
        for (int nt = 0; nt < 4; nt++)
#pragma unroll
            for (int c = 0; c < 4; c++) acc[mt][nt][c] = 0.0f;

    for (int kc = 0; kc < D_; kc += 32) {
        __syncthreads();   // previous k-step's fragment reads done
#pragma unroll
        for (int i = 0; i < 4; i++) {
            int f   = i * 256 + t;        // 0..1023
            int row = f >> 3;
            int c4  = (f & 7) * 4;
            float4 av = *(const float4*)(A + (size_t)(m0 + row) * D_ + kc + c4);
            uint32_t* da = &As[row * GP + c4];
            da[0] = f2tf(av.x); da[1] = f2tf(av.y); da[2] = f2tf(av.z); da[3] = f2tf(av.w);
            float4 wv = *(const float4*)(W + (size_t)(n0 + row) * D_ + kc + c4);
            uint32_t* dw = &Ws[row * GP + c4];
            dw[0] = f2tf(wv.x); dw[1] = f2tf(wv.y); dw[2] = f2tf(wv.z); dw[3] = f2tf(wv.w);
        }
        __syncthreads();

#pragma unroll
        for (int ks = 0; ks < 32; ks += 8) {
            uint32_t af[4][4];
#pragma unroll
            for (int mt = 0; mt < 4; mt++) {
                int r = wm + mt * 16;
                af[mt][0] = As[(r + g)     * GP + ks + tig];
                af[mt][1] = As[(r + g + 8) * GP + ks + tig];
                af[mt][2] = As[(r + g)     * GP + ks + tig + 4];
                af[mt][3] = As[(r + g + 8) * GP + ks + tig + 4];
            }
#pragma unroll
            for (int nt = 0; nt < 4; nt++) {
                int n = wn + nt * 8;
                uint32_t bf0 = Ws[(n + g) * GP + ks + tig];
                uint32_t bf1 = Ws[(n + g) * GP + ks + tig + 4];
#pragma unroll
                for (int mt = 0; mt < 4; mt++)
                    mma8(acc[mt][nt], af[mt][0], af[mt][1], af[mt][2], af[mt][3], bf0, bf1);
            }
        }
    }

    // Epilogue: bias + store (fragment layout: c0/c1 row g col 2tig, c2/c3 row g+8)
#pragma unroll
    for (int nt = 0; nt < 4; nt++) {
        int col = n0 + wn + nt * 8 + 2 * tig;
        float2 bi = *(const float2*)(bias + col);
#pragma unroll
        for (int mt = 0; mt < 4; mt++) {
            int r = m0 + wm + mt * 16 + g;
            float2 v0 = make_float2(acc[mt][nt][0] + bi.x, acc[mt][nt][1] + bi.y);
            *(float2*)(C + (size_t)r * D_ + col) = v0;
            float2 v1 = make_float2(acc[mt][nt][2] + bi.x, acc[mt][nt][3] + bi.y);
            *(float2*)(C + (size_t)(r + 8) * D_ + col) = v1;
        }
    }
}

// ---------------------------------------------------------------------------
// Upsample (linear, align_corners=False, factor 2): g_xq [B,L,D] -> g_q [B,Q,D]
// ---------------------------------------------------------------------------
__global__ void __launch_bounds__(256) upsample_kernel(
    const float* __restrict__ xq, float* __restrict__ qout)
{
    int idx = blockIdx.x * blockDim.x + threadIdx.x;   // float4 index
    int d4 = idx & 127;            // D/4 = 128
    int i  = (idx >> 7) & 4095;    // Q = 4096
    int b  = idx >> 19;

    const float4* xb = (const float4*)xq + (size_t)b * L_ * 128;
    float4 r;
    if (i == 0) {
        r = xb[d4];
    } else {
        float src = (i - 0.5f) * 0.5f;
        int i0 = (int)src;
        float w = src - (float)i0;
        int i1 = min(i0 + 1, L_ - 1);
        float4 a = xb[(size_t)i0 * 128 + d4];
        float4 c = xb[(size_t)i1 * 128 + d4];
        r.x = a.x + (c.x - a.x) * w;
        r.y = a.y + (c.y - a.y) * w;
        r.z = a.z + (c.z - a.z) * w;
        r.w = a.w + (c.w - a.w) * w;
    }
    ((float4*)qout)[idx] = r;
}

// ---------------------------------------------------------------------------
// Flash attention, tf32 mma. Grid (Q/128, H, B), 256 threads = 8 warps.
// Each warp: 16 q-rows x 64 k-cols (8 n-tiles of m16n8k8), hd=64 (8 k-steps).
// Online softmax in fragment space (row = 4-lane group -> shfl_xor 1,2).
// P re-fragmented via smem (warp-private rows -> __syncwarp only).
// Mask: k <= q (tall causal, Q=2L); only tiles with k0+63 > warp row base.
// ---------------------------------------------------------------------------
#define AP 68   // padded row stride (words): bank = 4*row + col  -> conflict-free

__global__ void __launch_bounds__(256) attn_mma_kernel(
    const float* __restrict__ q, const float* __restrict__ k,
    const float* __restrict__ v, float* __restrict__ out)
{
    extern __shared__ uint32_t sm[];
    uint32_t* Qs = sm;                 // [128][AP]
    uint32_t* Ks = Qs + 128 * AP;      // [64][AP]
    uint32_t* Vs = Ks + 64 * AP;       // [64][AP]
    uint32_t* Ps = Vs + 64 * AP;       // [128][AP]

    const int t    = threadIdx.x;
    const int lane = t & 31;
    const int wid  = t >> 5;
    const int g    = lane >> 2;
    const int tig  = lane & 3;

    const int q0 = blockIdx.x * 128;
    const int h  = blockIdx.y;
    const int b  = blockIdx.z;

    const float scale = 0.04419417382415922f;  // 512^-0.5

    const float* qb = q + (size_t)b * Q_ * D_ + h * HD_;
    const float* kb = k + (size_t)b * L_ * D_ + h * HD_;
    const float* vb = v + (size_t)b * L_ * D_ + h * HD_;

    // Load + scale + cvt Q tile (128 rows x 64 dims)
#pragma unroll
    for (int i = 0; i < 8; i++) {
        int f   = i * 256 + t;
        int row = f >> 4;
        int c4  = (f & 15) * 4;
        float4 qv = *(const float4*)(qb + (size_t)(q0 + row) * D_ + c4);
        uint32_t* d = &Qs[row * AP + c4];
        d[0] = f2tf(qv.x * scale); d[1] = f2tf(qv.y * scale);
        d[2] = f2tf(qv.z * scale); d[3] = f2tf(qv.w * scale);
    }

    float m0r = -1e30f, m1r = -1e30f, l0 = 0.0f, l1 = 0.0f;
    float oacc[8][4];
#pragma unroll
    for (int nt = 0; nt < 8; nt++)
#pragma unroll
        for (int c = 0; c < 4; c++) oacc[nt][c] = 0.0f;

    const int ntiles = min(q0 / 64 + 2, L_ / 64);
    const int qrow_w = q0 + wid * 16;    // warp's base q row

    for (int tile = 0; tile < ntiles; tile++) {
        const int k0 = tile * 64;
        __syncthreads();   // prior iteration done with Ks/Vs
#pragma unroll
        for (int i = 0; i < 4; i++) {
            int f   = i * 256 + t;
            int row = f >> 4;
            int c4  = (f & 15) * 4;
            float4 kv = *(const float4*)(kb + (size_t)(k0 + row) * D_ + c4);
            uint32_t* dk = &Ks[row * AP + c4];
            dk[0] = f2tf(kv.x); dk[1] = f2tf(kv.y); dk[2] = f2tf(kv.z); dk[3] = f2tf(kv.w);
            float4 vv = *(const float4*)(vb + (size_t)(k0 + row) * D_ + c4);
            uint32_t* dv = &Vs[row * AP + c4];
            dv[0] = f2tf(vv.x); dv[1] = f2tf(vv.y); dv[2] = f2tf(vv.z); dv[3] = f2tf(vv.w);
        }
        __syncthreads();

        // ---- S = Q @ K^T (16x64 per warp) ----
        float sacc[8][4];
#pragma unroll
        for (int nt = 0; nt < 8; nt++)
#pragma unroll
            for (int c = 0; c < 4; c++) sacc[nt][c] = 0.0f;

#pragma unroll
        for (int ks = 0; ks < 8; ks++) {
            int kk = ks * 8;
            uint32_t a0 = Qs[(wid * 16 + g)     * AP + kk + tig];
            uint32_t a1 = Qs[(wid * 16 + g + 8) * AP + kk + tig];
            uint32_t a2 = Qs[(wid * 16 + g)     * AP + kk + tig + 4];
            uint32_t a3 = Qs[(wid * 16 + g + 8) * AP + kk + tig + 4];
#pragma unroll
            for (int nt = 0; nt < 8; nt++) {
                uint32_t bf0 = Ks[(nt * 8 + g) * AP + kk + tig];
                uint32_t bf1 = Ks[(nt * 8 + g) * AP + kk + tig + 4];
                mma8(sacc[nt], a0, a1, a2, a3, bf0, bf1);
            }
        }

        // ---- causal mask (k <= q) ----
        if (k0 + 63 > qrow_w) {
            int r0 = qrow_w + g;
            int r1 = r0 + 8;
#pragma unroll
            for (int nt = 0; nt < 8; nt++) {
                int col = k0 + nt * 8 + 2 * tig;
                if (col     > r0) sacc[nt][0] = -1e30f;
                if (col + 1 > r0) sacc[nt][1] = -1e30f;
                if (col     > r1) sacc[nt][2] = -1e30f;
                if (col + 1 > r1) sacc[nt][3] = -1e30f;
            }
        }

        // ---- online softmax (rows: g -> c0/c1, g+8 -> c2/c3) ----
        float mx0 = -1e30f, mx1 = -1e30f;
#pragma unroll
        for (int nt = 0; nt < 8; nt++) {
            mx0 = fmaxf(mx0, fmaxf(sacc[nt][0], sacc[nt][1]));
            mx1 = fmaxf(mx1, fmaxf(sacc[nt][2], sacc[nt][3]));
        }
        mx0 = fmaxf(mx0, __shfl_xor_sync(0xffffffffu, mx0, 1));
        mx0 = fmaxf(mx0, __shfl_xor_sync(0xffffffffu, mx0, 2));
        mx1 = fmaxf(mx1, __shfl_xor_sync(0xffffffffu, mx1, 1));
        mx1 = fmaxf(mx1, __shfl_xor_sync(0xffffffffu, mx1, 2));

        float mn0 = fmaxf(m0r, mx0);
        float mn1 = fmaxf(m1r, mx1);
        float corr0 = __expf(m0r - mn0);
        float corr1 = __expf(m1r - mn1);
        float sum0 = 0.0f, sum1 = 0.0f;
#pragma unroll
        for (int nt = 0; nt < 8; nt++) {
            float p0 = __expf(sacc[nt][0] - mn0);
            float p1 = __expf(sacc[nt][1] - mn0);
            float p2 = __expf(sacc[nt][2] - mn1);
            float p3 = __expf(sacc[nt][3] - mn1);
            sacc[nt][0] = p0; sacc[nt][1] = p1; sacc[nt][2] = p2; sacc[nt][3] = p3;
            sum0 += p0 + p1;
            sum1 += p2 + p3;
        }
        sum0 += __shfl_xor_sync(0xffffffffu, sum0, 1);
        sum0 += __shfl_xor_sync(0xffffffffu, sum0, 2);
        sum1 += __shfl_xor_sync(0xffffffffu, sum1, 1);
        sum1 += __shfl_xor_sync(0xffffffffu, sum1, 2);
        l0 = l0 * corr0 + sum0;
        l1 = l1 * corr1 + sum1;
        m0r = mn0; m1r = mn1;
#pragma unroll
        for (int nt = 0; nt < 8; nt++) {
            oacc[nt][0] *= corr0; oacc[nt][1] *= corr0;
            oacc[nt][2] *= corr1; oacc[nt][3] *= corr1;
        }

        // ---- stage P (tf32) into warp-private Ps rows ----
#pragma unroll
        for (int nt = 0; nt < 8; nt++) {
            int col = nt * 8 + 2 * tig;
            uint32_t* p0 = &Ps[(wid * 16 + g) * AP + col];
            p0[0] = f2tf(sacc[nt][0]); p0[1] = f2tf(sacc[nt][1]);
            uint32_t* p1 = &Ps[(wid * 16 + g + 8) * AP + col];
            p1[0] = f2tf(sacc[nt][2]); p1[1] = f2tf(sacc[nt][3]);
        }
        __syncwarp();

        // ---- O += P @ V (contraction over 64 keys) ----
#pragma unroll
        for (int ks = 0; ks < 8; ks++) {
            int kk = ks * 8;
            uint32_t a0 = Ps[(wid * 16 + g)     * AP + kk + tig];
            uint32_t a1 = Ps[(wid * 16 + g + 8) * AP + kk + tig];
            uint32_t a2 = Ps[(wid * 16 + g)     * AP + kk + tig + 4];
            uint32_t a3 = Ps[(wid * 16 + g + 8) * AP + kk + tig + 4];
#pragma unroll
            for (int nt = 0; nt < 8; nt++) {
                uint32_t bf0 = Vs[(kk + tig)     * AP + nt * 8 + g];
                uint32_t bf1 = Vs[(kk + tig + 4) * AP + nt * 8 + g];
                mma8(oacc[nt], a0, a1, a2, a3, bf0, bf1);
            }
        }
    }

    // ---- epilogue: normalize, write [b, q, h*64+d] ----
    float inv0 = 1.0f / l0;
    float inv1 = 1.0f / l1;
    float* ob = out + ((size_t)b * Q_ + qrow_w) * D_ + h * HD_;
#pragma unroll
    for (int nt = 0; nt < 8; nt++) {
        int col = nt * 8 + 2 * tig;
        float2 v0 = make_float2(oacc[nt][0] * inv0, oacc[nt][1] * inv0);
        *(float2*)(ob + (size_t)g * D_ + col) = v0;
        float2 v1 = make_float2(oacc[nt][2] * inv1, oacc[nt][3] * inv1);
        *(float2*)(ob + (size_t)(g + 8) * D_ + col) = v1;
    }
}

// ---------------------------------------------------------------------------
// Launch
// ---------------------------------------------------------------------------
static const int ATT_SMEM = (128 + 64 + 64 + 128) * AP * 4;   // 104448 B

extern "C" void kernel_launch(void* const* d_in, const int* in_sizes, int n_in,
                              void* d_out, int out_size)
{
    const float* x  = (const float*)d_in[0];
    const float* Wq = (const float*)d_in[1];
    const float* bq = (const float*)d_in[2];
    const float* Wk = (const float*)d_in[3];
    const float* bk = (const float*)d_in[4];
    const float* Wv = (const float*)d_in[5];
    const float* bv = (const float*)d_in[6];
    const float* Wo = (const float*)d_in[7];
    const float* bo = (const float*)d_in[8];
    float* out = (float*)d_out;

    float *xq, *kk, *vv, *qq, *ao;
    cudaGetSymbolAddress((void**)&xq, g_xq);
    cudaGetSymbolAddress((void**)&kk, g_k);
    cudaGetSymbolAddress((void**)&vv, g_v);
    cudaGetSymbolAddress((void**)&qq, g_q);
    cudaGetSymbolAddress((void**)&ao, g_ao);

    cudaFuncSetAttribute(attn_mma_kernel,
                         cudaFuncAttributeMaxDynamicSharedMemorySize, ATT_SMEM);

    // Fused QKV projections: xq/k/v = x @ W^T + b   (M = 4096)
    dim3 gqkv(D_ / 128, (B_ * L_) / 128, 3);
    gemm_tf32_kernel<<<gqkv, 256>>>(x,
                                    Wq, bq, xq,
                                    Wk, bk, kk,
                                    Wv, bv, vv);

    // Upsample xq -> q
    upsample_kernel<<<(B_ * Q_ * D_ / 4) / 256, 256>>>(xq, qq);

    // Flash attention (tf32 mma)
    attn_mma_kernel<<<dim3(Q_ / 128, H_, B_), 256, ATT_SMEM>>>(qq, kk, vv, ao);

    // Output projection: out = ao @ Wo^T + bo   (M = 8192)
    dim3 gout(D_ / 128, (B_ * Q_) / 128, 1);
    gemm_tf32_kernel<<<gout, 256>>>(ao,
                                    Wo, bo, out,
                                    Wo, bo, out,
                                    Wo, bo, out);
}

// round 5
// speedup vs baseline: 2.5992x; 1.0616x over previous
#include <cuda_runtime.h>
#include <cstdint>

// Problem constants
#define B_   2
#define L_   2048
#define Q_   4096
#define D_   512
#define H_   8
#define HD_  64

// ---------------------------------------------------------------------------
// Scratch (allocation-free: __device__ globals)
// ---------------------------------------------------------------------------
__device__ float g_xq[B_ * L_ * D_];   // x @ Wq^T + bq   (pre-upsample)
__device__ float g_k [B_ * L_ * D_];
__device__ float g_v [B_ * L_ * D_];
__device__ float g_ao[B_ * Q_ * D_];   // attention output

// ---------------------------------------------------------------------------
// tf32 helpers
// ---------------------------------------------------------------------------
__device__ __forceinline__ uint32_t f2tf(float f) {
    uint32_t u;
    asm("cvt.rna.tf32.f32 %0, %1;" : "=r"(u) : "f"(f));
    return u;
}

// D(16x8) += A(16x8,row) * B(8x8,col)   tf32 inputs, fp32 accum
__device__ __forceinline__ void mma8(float* c,
                                     uint32_t a0, uint32_t a1, uint32_t a2, uint32_t a3,
                                     uint32_t b0, uint32_t b1) {
    asm volatile(
        "mma.sync.aligned.m16n8k8.row.col.f32.tf32.tf32.f32 "
        "{%0,%1,%2,%3}, {%4,%5,%6,%7}, {%8,%9}, {%0,%1,%2,%3};"
        : "+f"(c[0]), "+f"(c[1]), "+f"(c[2]), "+f"(c[3])
        : "r"(a0), "r"(a1), "r"(a2), "r"(a3), "r"(b0), "r"(b1));
}

// ---------------------------------------------------------------------------
// tf32 GEMM: C[m][n] = sum_k A[m][k]*W[n][k] + bias[n].  K = N = 512 fixed.
// Block tile 128x128, k-chunk 64. 256 threads = 8 warps (2 m x 4 n),
// warp tile 64x32 => 4 m-tiles x 4 n-tiles of m16n8k8.
// Smem stride 68 words -> all fragment LDS and fill STS conflict-free.
// grid.z picks one of 3 (W,bias,C) triples (fused QKV).
// ---------------------------------------------------------------------------
#define GP 68

__global__ void __launch_bounds__(256, 2) gemm_tf32_kernel(
    const float* __restrict__ A,
    const float* __restrict__ W0, const float* __restrict__ b0_, float* __restrict__ C0,
    const float* __restrict__ W1, const float* __restrict__ b1_, float* __restrict__ C1,
    const float* __restrict__ W2, const float* __restrict__ b2_, float* __restrict__ C2)
{
    const float* W = W0; const float* bias = b0_; float* C = C0;
    if (blockIdx.z == 1) { W = W1; bias = b1_; C = C1; }
    else if (blockIdx.z == 2) { W = W2; bias = b2_; C = C2; }

    extern __shared__ uint32_t gsm[];
    uint32_t* As = gsm;               // [128][GP]
    uint32_t* Ws = gsm + 128 * GP;    // [128][GP]

    const int t    = threadIdx.x;
    const int lane = t & 31;
    const int wid  = t >> 5;
    const int g    = lane >> 2;   // group (row within fragment)
    const int tig  = lane & 3;    // thread-in-group
    const int wm   = (wid & 1) * 64;   // warp m offset in tile
    const int wn   = (wid >> 1) * 32;  // warp n offset in tile

    const int m0 = blockIdx.y * 128;
    const int n0 = blockIdx.x * 128;

    float acc[4][4][4];
#pragma unroll
    for (int mt = 0; mt < 4; mt++)
#pragma unroll
        for (int nt = 0; nt < 4; nt++)
#pragma unroll
            for (int c = 0; c < 4; c++) acc[mt][nt][c] = 0.0f;

    for (int kc = 0; kc < D_; kc += 64) {
        __syncthreads();   // previous chunk's fragment reads done
#pragma unroll
        for (int i = 0; i < 8; i++) {
            int f   = i * 256 + t;        // 0..2047
            int row = f >> 4;             // 0..127
            int c4  = (f & 15) * 4;       // 0..60
            float4 av = *(const float4*)(A + (size_t)(m0 + row) * D_ + kc + c4);
            uint4 ua;
            ua.x = f2tf(av.x); ua.y = f2tf(av.y); ua.z = f2tf(av.z); ua.w = f2tf(av.w);
            *(uint4*)&As[row * GP + c4] = ua;
            float4 wv = *(const float4*)(W + (size_t)(n0 + row) * D_ + kc + c4);
            uint4 uw;
            uw.x = f2tf(wv.x); uw.y = f2tf(wv.y); uw.z = f2tf(wv.z); uw.w = f2tf(wv.w);
            *(uint4*)&Ws[row * GP + c4] = uw;
        }
        __syncthreads();

#pragma unroll
        for (int ks = 0; ks < 64; ks += 8) {
            uint32_t af[4][4];
#pragma unroll
            for (int mt = 0; mt < 4; mt++) {
                int r = wm + mt * 16;
                af[mt][0] = As[(r + g)     * GP + ks + tig];
                af[mt][1] = As[(r + g + 8) * GP + ks + tig];
                af[mt][2] = As[(r + g)     * GP + ks + tig + 4];
                af[mt][3] = As[(r + g + 8) * GP + ks + tig + 4];
            }
#pragma unroll
            for (int nt = 0; nt < 4; nt++) {
                int n = wn + nt * 8;
                uint32_t bf0 = Ws[(n + g) * GP + ks + tig];
                uint32_t bf1 = Ws[(n + g) * GP + ks + tig + 4];
#pragma unroll
                for (int mt = 0; mt < 4; mt++)
                    mma8(acc[mt][nt], af[mt][0], af[mt][1], af[mt][2], af[mt][3], bf0, bf1);
            }
        }
    }

    // Epilogue: bias + store (fragment: c0/c1 row g col 2tig, c2/c3 row g+8)
#pragma unroll
    for (int nt = 0; nt < 4; nt++) {
        int col = n0 + wn + nt * 8 + 2 * tig;
        float2 bi = *(const float2*)(bias + col);
#pragma unroll
        for (int mt = 0; mt < 4; mt++) {
            int r = m0 + wm + mt * 16 + g;
            float2 v0 = make_float2(acc[mt][nt][0] + bi.x, acc[mt][nt][1] + bi.y);
            *(float2*)(C + (size_t)r * D_ + col) = v0;
            float2 v1 = make_float2(acc[mt][nt][2] + bi.x, acc[mt][nt][3] + bi.y);
            *(float2*)(C + (size_t)(r + 8) * D_ + col) = v1;
        }
    }
}

// ---------------------------------------------------------------------------
// Flash attention, tf32 mma, fused upsample on Q.
// Grid (Q/64, H, B) with REVERSED q-block order (heavy causal blocks first).
// 128 threads = 4 warps; warp w: q rows 16w..16w+15, 64 k-cols per tile.
// Smem stride AP=72 words: all fragment LDS conflict-free.
// Qs/Ps use octet-interleaved columns (orig col c -> (c&3)*2+(c>>2)) so
// A-fragments load as uint2 {k=tig, k=tig+4}. Ks/Vs plain.
// ---------------------------------------------------------------------------
#define AP 72

__global__ void __launch_bounds__(128, 3) attn_mma_kernel(
    const float* __restrict__ xq, const float* __restrict__ k,
    const float* __restrict__ v, float* __restrict__ out)
{
    extern __shared__ uint32_t sm[];
    uint32_t* Qs = sm;                // [64][AP] interleaved
    uint32_t* Ks = Qs + 64 * AP;      // [64][AP] plain
    uint32_t* Vs = Ks + 64 * AP;      // [64][AP] plain
    uint32_t* Ps = Vs + 64 * AP;      // [64][AP] interleaved

    const int t    = threadIdx.x;
    const int lane = t & 31;
    const int wid  = t >> 5;
    const int g    = lane >> 2;
    const int tig  = lane & 3;

    const int bx = gridDim.x - 1 - blockIdx.x;   // reversed schedule
    const int q0 = bx * 64;
    const int h  = blockIdx.y;
    const int b  = blockIdx.z;

    const float scale = 0.04419417382415922f;  // 512^-0.5

    const float* xqb = xq + (size_t)b * L_ * D_ + h * HD_;
    const float* kb  = k  + (size_t)b * L_ * D_ + h * HD_;
    const float* vb  = v  + (size_t)b * L_ * D_ + h * HD_;

    // ---- Q fill: fused linear upsample (x2) + scale + tf32 + interleave ----
#pragma unroll
    for (int i = 0; i < 8; i++) {
        int f    = i * 128 + t;       // 0..1023
        int row  = f >> 4;            // 0..63
        int c4   = (f & 15) * 4;      // 0..60
        int qrow = q0 + row;
        float4 val;
        if (qrow == 0) {
            val = *(const float4*)(xqb + c4);
        } else {
            float src = (qrow - 0.5f) * 0.5f;
            int i0 = (int)src;
            float w = src - (float)i0;
            int i1 = min(i0 + 1, L_ - 1);
            float4 a = *(const float4*)(xqb + (size_t)i0 * D_ + c4);
            float4 c = *(const float4*)(xqb + (size_t)i1 * D_ + c4);
            val.x = a.x + (c.x - a.x) * w;
            val.y = a.y + (c.y - a.y) * w;
            val.z = a.z + (c.z - a.z) * w;
            val.w = a.w + (c.w - a.w) * w;
        }
        // interleave: cols c4..c4+3 are (par=0: octet cols 0-3 -> pos 0,2,4,6 |
        //                                par=1: octet cols 4-7 -> pos 1,3,5,7)
        int oct = c4 >> 3;
        int par = (c4 >> 2) & 1;
        uint32_t* dst = &Qs[row * AP + oct * 8 + par];
        dst[0] = f2tf(val.x * scale);
        dst[2] = f2tf(val.y * scale);
        dst[4] = f2tf(val.z * scale);
        dst[6] = f2tf(val.w * scale);
    }

    float m0r = -1e30f, m1r = -1e30f, l0 = 0.0f, l1 = 0.0f;
    float oacc[8][4];
#pragma unroll
    for (int nt = 0; nt < 8; nt++)
#pragma unroll
        for (int c = 0; c < 4; c++) oacc[nt][c] = 0.0f;

    const int ntiles = min(bx + 1, L_ / 64);
    const int qrow_w = q0 + wid * 16;    // warp's base q row

    for (int tile = 0; tile < ntiles; tile++) {
        const int k0 = tile * 64;
        __syncthreads();   // prior iteration done with Ks/Vs
#pragma unroll
        for (int i = 0; i < 8; i++) {
            int f   = i * 128 + t;
            int row = f >> 4;
            int c4  = (f & 15) * 4;
            float4 kv = *(const float4*)(kb + (size_t)(k0 + row) * D_ + c4);
            uint4 uk;
            uk.x = f2tf(kv.x); uk.y = f2tf(kv.y); uk.z = f2tf(kv.z); uk.w = f2tf(kv.w);
            *(uint4*)&Ks[row * AP + c4] = uk;
            float4 vv = *(const float4*)(vb + (size_t)(k0 + row) * D_ + c4);
            uint4 uv;
            uv.x = f2tf(vv.x); uv.y = f2tf(vv.y); uv.z = f2tf(vv.z); uv.w = f2tf(vv.w);
            *(uint4*)&Vs[row * AP + c4] = uv;
        }
        __syncthreads();

        // ---- S = Q @ K^T (16x64 per warp) ----
        float sacc[8][4];
#pragma unroll
        for (int nt = 0; nt < 8; nt++)
#pragma unroll
            for (int c = 0; c < 4; c++) sacc[nt][c] = 0.0f;

#pragma unroll
        for (int ks = 0; ks < 8; ks++) {
            int kk = ks * 8;
            uint2 a01 = *(const uint2*)&Qs[(wid * 16 + g)     * AP + kk + 2 * tig];
            uint2 a23 = *(const uint2*)&Qs[(wid * 16 + g + 8) * AP + kk + 2 * tig];
#pragma unroll
            for (int nt = 0; nt < 8; nt++) {
                uint32_t bf0 = Ks[(nt * 8 + g) * AP + kk + tig];
                uint32_t bf1 = Ks[(nt * 8 + g) * AP + kk + tig + 4];
                mma8(sacc[nt], a01.x, a23.x, a01.y, a23.y, bf0, bf1);
            }
        }

        // ---- causal mask (k <= q), only the diagonal tile ----
        if (k0 == q0) {
            int r0 = qrow_w + g;
            int r1 = r0 + 8;
#pragma unroll
            for (int nt = 0; nt < 8; nt++) {
                int col = k0 + nt * 8 + 2 * tig;
                if (col     > r0) sacc[nt][0] = -1e30f;
                if (col + 1 > r0) sacc[nt][1] = -1e30f;
                if (col     > r1) sacc[nt][2] = -1e30f;
                if (col + 1 > r1) sacc[nt][3] = -1e30f;
            }
        }

        // ---- online softmax (rows: g -> c0/c1, g+8 -> c2/c3) ----
        float mx0 = -1e30f, mx1 = -1e30f;
#pragma unroll
        for (int nt = 0; nt < 8; nt++) {
            mx0 = fmaxf(mx0, fmaxf(sacc[nt][0], sacc[nt][1]));
            mx1 = fmaxf(mx1, fmaxf(sacc[nt][2], sacc[nt][3]));
        }
        mx0 = fmaxf(mx0, __shfl_xor_sync(0xffffffffu, mx0, 1));
        mx0 = fmaxf(mx0, __shfl_xor_sync(0xffffffffu, mx0, 2));
        mx1 = fmaxf(mx1, __shfl_xor_sync(0xffffffffu, mx1, 1));
        mx1 = fmaxf(mx1, __shfl_xor_sync(0xffffffffu, mx1, 2));

        float mn0 = fmaxf(m0r, mx0);
        float mn1 = fmaxf(m1r, mx1);
        float corr0 = __expf(m0r - mn0);
        float corr1 = __expf(m1r - mn1);
        float sum0 = 0.0f, sum1 = 0.0f;
#pragma unroll
        for (int nt = 0; nt < 8; nt++) {
            float p0 = __expf(sacc[nt][0] - mn0);
            float p1 = __expf(sacc[nt][1] - mn0);
            float p2 = __expf(sacc[nt][2] - mn1);
            float p3 = __expf(sacc[nt][3] - mn1);
            sacc[nt][0] = p0; sacc[nt][1] = p1; sacc[nt][2] = p2; sacc[nt][3] = p3;
            sum0 += p0 + p1;
            sum1 += p2 + p3;
        }
        sum0 += __shfl_xor_sync(0xffffffffu, sum0, 1);
        sum0 += __shfl_xor_sync(0xffffffffu, sum0, 2);
        sum1 += __shfl_xor_sync(0xffffffffu, sum1, 1);
        sum1 += __shfl_xor_sync(0xffffffffu, sum1, 2);
        l0 = l0 * corr0 + sum0;
        l1 = l1 * corr1 + sum1;
        m0r = mn0; m1r = mn1;
#pragma unroll
        for (int nt = 0; nt < 8; nt++) {
            oacc[nt][0] *= corr0; oacc[nt][1] *= corr0;
            oacc[nt][2] *= corr1; oacc[nt][3] *= corr1;
        }

        // ---- stage P (tf32) into warp-private Ps rows, interleaved ----
        // owned cols 2tig,2tig+1 -> interleaved positions pc, pc+2
        const int pc = ((2 * tig) & 3) * 2 + (tig >> 1);
#pragma unroll
        for (int nt = 0; nt < 8; nt++) {
            uint32_t* p0 = &Ps[(wid * 16 + g) * AP + nt * 8];
            p0[pc]     = f2tf(sacc[nt][0]);
            p0[pc + 2] = f2tf(sacc[nt][1]);
            uint32_t* p1 = &Ps[(wid * 16 + g + 8) * AP + nt * 8];
            p1[pc]     = f2tf(sacc[nt][2]);
            p1[pc + 2] = f2tf(sacc[nt][3]);
        }
        __syncwarp();

        // ---- O += P @ V (contraction over 64 keys) ----
#pragma unroll
        for (int ks = 0; ks < 8; ks++) {
            int kk = ks * 8;
            uint2 a01 = *(const uint2*)&Ps[(wid * 16 + g)     * AP + kk + 2 * tig];
            uint2 a23 = *(const uint2*)&Ps[(wid * 16 + g + 8) * AP + kk + 2 * tig];
#pragma unroll
            for (int nt = 0; nt < 8; nt++) {
                uint32_t bf0 = Vs[(kk + tig)     * AP + nt * 8 + g];
                uint32_t bf1 = Vs[(kk + tig + 4) * AP + nt * 8 + g];
                mma8(oacc[nt], a01.x, a23.x, a01.y, a23.y, bf0, bf1);
            }
        }
        __syncwarp();   // PV reads of Ps done before next tile overwrites
    }

    // ---- epilogue: normalize, write [b, q, h*64+d] ----
    float inv0 = 1.0f / l0;
    float inv1 = 1.0f / l1;
    float* ob = out + ((size_t)b * Q_ + qrow_w) * D_ + h * HD_;
#pragma unroll
    for (int nt = 0; nt < 8; nt++) {
        int col = nt * 8 + 2 * tig;
        float2 v0 = make_float2(oacc[nt][0] * inv0, oacc[nt][1] * inv0);
        *(float2*)(ob + (size_t)g * D_ + col) = v0;
        float2 v1 = make_float2(oacc[nt][2] * inv1, oacc[nt][3] * inv1);
        *(float2*)(ob + (size_t)(g + 8) * D_ + col) = v1;
    }
}

// ---------------------------------------------------------------------------
// Launch
// ---------------------------------------------------------------------------
static const int GEMM_SMEM = 2 * 128 * GP * 4;        // 69632 B
static const int ATT_SMEM  = 4 * 64 * AP * 4;         // 73728 B

extern "C" void kernel_launch(void* const* d_in, const int* in_sizes, int n_in,
                              void* d_out, int out_size)
{
    const float* x  = (const float*)d_in[0];
    const float* Wq = (const float*)d_in[1];
    const float* bq = (const float*)d_in[2];
    const float* Wk = (const float*)d_in[3];
    const float* bk = (const float*)d_in[4];
    const float* Wv = (const float*)d_in[5];
    const float* bv = (const float*)d_in[6];
    const float* Wo = (const float*)d_in[7];
    const float* bo = (const float*)d_in[8];
    float* out = (float*)d_out;

    float *xq, *kk, *vv, *ao;
    cudaGetSymbolAddress((void**)&xq, g_xq);
    cudaGetSymbolAddress((void**)&kk, g_k);
    cudaGetSymbolAddress((void**)&vv, g_v);
    cudaGetSymbolAddress((void**)&ao, g_ao);

    cudaFuncSetAttribute(gemm_tf32_kernel,
                         cudaFuncAttributeMaxDynamicSharedMemorySize, GEMM_SMEM);
    cudaFuncSetAttribute(attn_mma_kernel,
                         cudaFuncAttributeMaxDynamicSharedMemorySize, ATT_SMEM);

    // Fused QKV projections: xq/k/v = x @ W^T + b   (M = 4096)
    dim3 gqkv(D_ / 128, (B_ * L_) / 128, 3);
    gemm_tf32_kernel<<<gqkv, 256, GEMM_SMEM>>>(x,
                                               Wq, bq, xq,
                                               Wk, bk, kk,
                                               Wv, bv, vv);

    // Flash attention (tf32 mma, fused upsample, reversed schedule)
    attn_mma_kernel<<<dim3(Q_ / 64, H_, B_), 128, ATT_SMEM>>>(xq, kk, vv, ao);

    // Output projection: out = ao @ Wo^T + bo   (M = 8192)
    dim3 gout(D_ / 128, (B_ * Q_) / 128, 1);
    gemm_tf32_kernel<<<gout, 256, GEMM_SMEM>>>(ao,
                                               Wo, bo, out,
                                               Wo, bo, out,
                                               Wo, bo, out);
}

// round 6
// speedup vs baseline: 3.2751x; 1.2601x over previous
#include <cuda_runtime.h>
#include <cstdint>

// Problem constants
#define B_   2
#define L_   2048
#define Q_   4096
#define D_   512
#define H_   8
#define HD_  64

// ---------------------------------------------------------------------------
// Scratch (allocation-free: __device__ globals). All tensors that feed an MMA
// are stored as tf32-pre-rounded fp32 bit patterns, so cp.async can move them
// raw into smem and mma's truncation == round-to-nearest (numerics preserved).
// ---------------------------------------------------------------------------
__device__ float g_x [B_ * L_ * D_];   // tf32-rounded x
__device__ float g_wq[D_ * D_];
__device__ float g_wk[D_ * D_];
__device__ float g_wv[D_ * D_];
__device__ float g_wo[D_ * D_];
__device__ float g_xq[B_ * L_ * D_];   // x @ Wq^T + bq (rounded, pre-upsample)
__device__ float g_k [B_ * L_ * D_];
__device__ float g_v [B_ * L_ * D_];
__device__ float g_ao[B_ * Q_ * D_];   // attention output (rounded)

// ---------------------------------------------------------------------------
// Helpers
// ---------------------------------------------------------------------------
__device__ __forceinline__ uint32_t f2tf(float f) {
    uint32_t u;
    asm("cvt.rna.tf32.f32 %0, %1;" : "=r"(u) : "f"(f));
    return u;
}
__device__ __forceinline__ float tfrnd(float f) { return __uint_as_float(f2tf(f)); }

__device__ __forceinline__ void mma8(float* c,
                                     uint32_t a0, uint32_t a1, uint32_t a2, uint32_t a3,
                                     uint32_t b0, uint32_t b1) {
    asm volatile(
        "mma.sync.aligned.m16n8k8.row.col.f32.tf32.tf32.f32 "
        "{%0,%1,%2,%3}, {%4,%5,%6,%7}, {%8,%9}, {%0,%1,%2,%3};"
        : "+f"(c[0]), "+f"(c[1]), "+f"(c[2]), "+f"(c[3])
        : "r"(a0), "r"(a1), "r"(a2), "r"(a3), "r"(b0), "r"(b1));
}

__device__ __forceinline__ void cpasync16(uint32_t dst, const void* src) {
    asm volatile("cp.async.cg.shared.global [%0], [%1], 16;" :: "r"(dst), "l"(src));
}
__device__ __forceinline__ void cpcommit() { asm volatile("cp.async.commit_group;"); }
__device__ __forceinline__ void cpwait0()  { asm volatile("cp.async.wait_group 0;" ::: "memory"); }

// ---------------------------------------------------------------------------
// Prepass: tf32-round x and the four weight matrices into scratch.
// ---------------------------------------------------------------------------
__global__ void __launch_bounds__(256) round_kernel(
    const float* __restrict__ src, float* __restrict__ dst, int n4)
{
    int i = blockIdx.x * 256 + threadIdx.x;
    if (i < n4) {
        float4 v = ((const float4*)src)[i];
        v.x = tfrnd(v.x); v.y = tfrnd(v.y); v.z = tfrnd(v.z); v.w = tfrnd(v.w);
        ((float4*)dst)[i] = v;
    }
}

__global__ void __launch_bounds__(256) round_w_kernel(
    const float* __restrict__ w0, float* __restrict__ d0,
    const float* __restrict__ w1, float* __restrict__ d1,
    const float* __restrict__ w2, float* __restrict__ d2,
    const float* __restrict__ w3, float* __restrict__ d3)
{
    const float* s = w0; float* d = d0;
    if (blockIdx.y == 1) { s = w1; d = d1; }
    else if (blockIdx.y == 2) { s = w2; d = d2; }
    else if (blockIdx.y == 3) { s = w3; d = d3; }
    int i = blockIdx.x * 256 + threadIdx.x;   // 65536 float4 per W
    float4 v = ((const float4*)s)[i];
    v.x = tfrnd(v.x); v.y = tfrnd(v.y); v.z = tfrnd(v.z); v.w = tfrnd(v.w);
    ((float4*)d)[i] = v;
}

// ---------------------------------------------------------------------------
// tf32 GEMM with cp.async 2-stage pipeline. C = A @ W^T + bias. K = N = 512.
// Block 128x128, k-chunk 32 (x2 buffers). 256 threads = 8 warps (2m x 4n).
// Inputs are tf32-pre-rounded; smem holds raw bits (stride 36 words,
// conflict-free fragment LDS). roundOut: tf32-round C (for tensors feeding
// later MMAs). grid.z picks one of 3 (W,bias,C) triples.
// ---------------------------------------------------------------------------
#define GST 36
#define GBUF (128 * GST)

__global__ void __launch_bounds__(256, 2) gemm_tf32_cp(
    const float* __restrict__ A,
    const float* __restrict__ W0, const float* __restrict__ b0_, float* __restrict__ C0,
    const float* __restrict__ W1, const float* __restrict__ b1_, float* __restrict__ C1,
    const float* __restrict__ W2, const float* __restrict__ b2_, float* __restrict__ C2,
    int roundOut)
{
    const float* W = W0; const float* bias = b0_; float* C = C0;
    if (blockIdx.z == 1) { W = W1; bias = b1_; C = C1; }
    else if (blockIdx.z == 2) { W = W2; bias = b2_; C = C2; }

    extern __shared__ uint32_t gsm[];   // [Abuf0][Abuf1][Wbuf0][Wbuf1], each GBUF
    const uint32_t sbase = (uint32_t)__cvta_generic_to_shared(gsm);

    const int t    = threadIdx.x;
    const int lane = t & 31;
    const int wid  = t >> 5;
    const int g    = lane >> 2;
    const int tig  = lane & 3;
    const int wm   = (wid & 1) * 64;
    const int wn   = (wid >> 1) * 32;

    const int m0 = blockIdx.y * 128;
    const int n0 = blockIdx.x * 128;

    // fill coords: 4 float4 per array per chunk per thread
    const int fr0 = t >> 3;          // base row (+32 per i)
    const int fc  = (t & 7) * 4;     // word col in chunk
    const float* Asrc = A + (size_t)(m0 + fr0) * D_ + fc;
    const float* Wsrc = W + (size_t)(n0 + fr0) * D_ + fc;
    const uint32_t dW = fr0 * GST + fc;

    float acc[4][4][4];
#pragma unroll
    for (int mt = 0; mt < 4; mt++)
#pragma unroll
        for (int nt = 0; nt < 4; nt++)
#pragma unroll
            for (int c = 0; c < 4; c++) acc[mt][nt][c] = 0.0f;

    // prologue: chunk 0 -> buf 0
#pragma unroll
    for (int i = 0; i < 4; i++) {
        cpasync16(sbase + (dW + i * 32 * GST) * 4,            Asrc + (size_t)i * 32 * D_);
        cpasync16(sbase + (2 * GBUF + dW + i * 32 * GST) * 4, Wsrc + (size_t)i * 32 * D_);
    }
    cpcommit();

    for (int ic = 0; ic < 16; ic++) {
        cpwait0();
        __syncthreads();
        if (ic < 15) {
            const int bf = (ic + 1) & 1;
            const size_t ko = (size_t)(ic + 1) * 32;
#pragma unroll
            for (int i = 0; i < 4; i++) {
                cpasync16(sbase + (bf * GBUF + dW + i * 32 * GST) * 4,
                          Asrc + (size_t)i * 32 * D_ + ko);
                cpasync16(sbase + ((2 + bf) * GBUF + dW + i * 32 * GST) * 4,
                          Wsrc + (size_t)i * 32 * D_ + ko);
            }
            cpcommit();
        }
        const uint32_t* As = gsm + (ic & 1) * GBUF;
        const uint32_t* Ws = gsm + (2 + (ic & 1)) * GBUF;

#pragma unroll
        for (int ks = 0; ks < 32; ks += 8) {
            uint32_t af[4][4];
#pragma unroll
            for (int mt = 0; mt < 4; mt++) {
                int r = wm + mt * 16;
                af[mt][0] = As[(r + g)     * GST + ks + tig];
                af[mt][1] = As[(r + g + 8) * GST + ks + tig];
                af[mt][2] = As[(r + g)     * GST + ks + tig + 4];
                af[mt][3] = As[(r + g + 8) * GST + ks + tig + 4];
            }
#pragma unroll
            for (int nt = 0; nt < 4; nt++) {
                int n = wn + nt * 8;
                uint32_t bf0 = Ws[(n + g) * GST + ks + tig];
                uint32_t bf1 = Ws[(n + g) * GST + ks + tig + 4];
#pragma unroll
                for (int mt = 0; mt < 4; mt++)
                    mma8(acc[mt][nt], af[mt][0], af[mt][1], af[mt][2], af[mt][3], bf0, bf1);
            }
        }
    }

    // Epilogue: bias (+ optional tf32 rounding) + store
#pragma unroll
    for (int nt = 0; nt < 4; nt++) {
        int col = n0 + wn + nt * 8 + 2 * tig;
        float2 bi = *(const float2*)(bias + col);
#pragma unroll
        for (int mt = 0; mt < 4; mt++) {
            int r = m0 + wm + mt * 16 + g;
            float2 v0 = make_float2(acc[mt][nt][0] + bi.x, acc[mt][nt][1] + bi.y);
            float2 v1 = make_float2(acc[mt][nt][2] + bi.x, acc[mt][nt][3] + bi.y);
            if (roundOut) {
                v0.x = tfrnd(v0.x); v0.y = tfrnd(v0.y);
                v1.x = tfrnd(v1.x); v1.y = tfrnd(v1.y);
            }
            *(float2*)(C + (size_t)r * D_ + col)       = v0;
            *(float2*)(C + (size_t)(r + 8) * D_ + col) = v1;
        }
    }
}

// ---------------------------------------------------------------------------
// Flash attention: tf32 mma, fused upsample on Q, cp.async double-buffered K/V,
// Q fragments register-resident, exp2-domain softmax, reversed causal schedule.
// Grid (Q/64, H, B), 128 threads = 4 warps; warp w: q rows 16w..16w+15.
// K/V smem rows swizzled (+4 words when row bit2 set) -> conflict-free B LDS.
// ---------------------------------------------------------------------------
#define AP 72
#define ABUF (64 * AP)

__global__ void __launch_bounds__(128, 2) attn_cp_kernel(
    const float* __restrict__ xq, const float* __restrict__ k,
    const float* __restrict__ v, float* __restrict__ out)
{
    extern __shared__ uint32_t sm[];   // [Kbuf0][Kbuf1][Vbuf0][Vbuf1][Ps]
    const uint32_t sbase = (uint32_t)__cvta_generic_to_shared(sm);
    uint32_t* Ps = sm + 4 * ABUF;      // also Q staging before the loop

    const int t    = threadIdx.x;
    const int lane = t & 31;
    const int wid  = t >> 5;
    const int g    = lane >> 2;
    const int tig  = lane & 3;

    const int bx = gridDim.x - 1 - blockIdx.x;   // reversed schedule
    const int q0 = bx * 64;
    const int h  = blockIdx.y;
    const int b  = blockIdx.z;

    // 512^-0.5 * log2(e): softmax done in exp2 domain
    const float scale = 0.04419417382415922f * 1.44269504088896340f;

    const float* xqb = xq + (size_t)b * L_ * D_ + h * HD_;
    const float* kb  = k  + (size_t)b * L_ * D_ + h * HD_;
    const float* vb  = v  + (size_t)b * L_ * D_ + h * HD_;

    // K/V fill coords: 8 float4 per array per tile per thread
    const int kr0 = t >> 4;          // base row (+8 per i)
    const int kc4 = (t & 15) * 4;

    // ---- prologue: issue tile 0 -> buf 0 ----
#pragma unroll
    for (int i = 0; i < 8; i++) {
        int row = kr0 + i * 8;
        uint32_t d = (row * AP + ((row >> 2) & 1) * 4 + kc4) * 4;
        cpasync16(sbase + d,                kb + (size_t)row * D_ + kc4);
        cpasync16(sbase + 2 * ABUF * 4 + d, vb + (size_t)row * D_ + kc4);
    }
    cpcommit();

    // ---- Q staging: fused upsample + scale + tf32, interleaved into Ps ----
#pragma unroll
    for (int i = 0; i < 8; i++) {
        int f    = i * 128 + t;
        int row  = f >> 4;
        int c4   = (f & 15) * 4;
        int qrow = q0 + row;
        float4 val;
        if (qrow == 0) {
            val = *(const float4*)(xqb + c4);
        } else {
            float src = (qrow - 0.5f) * 0.5f;
            int i0 = (int)src;
            float w = src - (float)i0;
            int i1 = min(i0 + 1, L_ - 1);
            float4 a = *(const float4*)(xqb + (size_t)i0 * D_ + c4);
            float4 c = *(const float4*)(xqb + (size_t)i1 * D_ + c4);
            val.x = a.x + (c.x - a.x) * w;
            val.y = a.y + (c.y - a.y) * w;
            val.z = a.z + (c.z - a.z) * w;
            val.w = a.w + (c.w - a.w) * w;
        }
        int oct = c4 >> 3;
        int par = (c4 >> 2) & 1;
        uint32_t* dst = &Ps[row * AP + oct * 8 + par];
        dst[0] = f2tf(val.x * scale);
        dst[2] = f2tf(val.y * scale);
        dst[4] = f2tf(val.z * scale);
        dst[6] = f2tf(val.w * scale);
    }
    __syncthreads();

    // ---- Q fragments to registers (then Ps is free for P staging) ----
    uint32_t qf[8][4];
#pragma unroll
    for (int ks = 0; ks < 8; ks++) {
        int kk = ks * 8;
        uint2 a01 = *(const uint2*)&Ps[(wid * 16 + g)     * AP + kk + 2 * tig];
        uint2 a23 = *(const uint2*)&Ps[(wid * 16 + g + 8) * AP + kk + 2 * tig];
        qf[ks][0] = a01.x; qf[ks][1] = a23.x; qf[ks][2] = a01.y; qf[ks][3] = a23.y;
    }

    float m0r = -1e30f, m1r = -1e30f, l0 = 0.0f, l1 = 0.0f;
    float oacc[8][4];
#pragma unroll
    for (int nt = 0; nt < 8; nt++)
#pragma unroll
        for (int c = 0; c < 4; c++) oacc[nt][c] = 0.0f;

    const int ntiles = min(bx + 1, L_ / 64);
    const int qrow_w = q0 + wid * 16;
    const int gsw    = ((g >> 2) & 1) * 4;   // row-swizzle shift for K B-frags

    for (int tile = 0; tile < ntiles; tile++) {
        const int k0 = tile * 64;
        cpwait0();
        __syncthreads();   // data visible; all warps done with prev buffers + Ps

        if (tile + 1 < ntiles) {
            const int bf = (tile + 1) & 1;
            const size_t ko = (size_t)(k0 + 64) * D_;
#pragma unroll
            for (int i = 0; i < 8; i++) {
                int row = kr0 + i * 8;
                uint32_t d = (row * AP + ((row >> 2) & 1) * 4 + kc4) * 4;
                cpasync16(sbase + bf * ABUF * 4 + d,       kb + ko + (size_t)row * D_ + kc4);
                cpasync16(sbase + (2 + bf) * ABUF * 4 + d, vb + ko + (size_t)row * D_ + kc4);
            }
            cpcommit();
        }

        const uint32_t* Ks = sm + (tile & 1) * ABUF;
        const uint32_t* Vs = sm + (2 + (tile & 1)) * ABUF;

        // ---- S = Q @ K^T (16x64 per warp) ----
        float sacc[8][4];
#pragma unroll
        for (int nt = 0; nt < 8; nt++)
#pragma unroll
            for (int c = 0; c < 4; c++) sacc[nt][c] = 0.0f;

#pragma unroll
        for (int ks = 0; ks < 8; ks++) {
            int kk = ks * 8;
#pragma unroll
            for (int nt = 0; nt < 8; nt++) {
                const uint32_t* kr = &Ks[(nt * 8 + g) * AP + gsw + kk + tig];
                mma8(sacc[nt], qf[ks][0], qf[ks][1], qf[ks][2], qf[ks][3], kr[0], kr[4]);
            }
        }

        // ---- causal mask (diagonal tile only) ----
        if (k0 == q0) {
            int r0 = qrow_w + g;
            int r1 = r0 + 8;
#pragma unroll
            for (int nt = 0; nt < 8; nt++) {
                int col = k0 + nt * 8 + 2 * tig;
                if (col     > r0) sacc[nt][0] = -1e30f;
                if (col + 1 > r0) sacc[nt][1] = -1e30f;
                if (col     > r1) sacc[nt][2] = -1e30f;
                if (col + 1 > r1) sacc[nt][3] = -1e30f;
            }
        }

        // ---- online softmax (exp2 domain) ----
        float mx0 = -1e30f, mx1 = -1e30f;
#pragma unroll
        for (int nt = 0; nt < 8; nt++) {
            mx0 = fmaxf(mx0, fmaxf(sacc[nt][0], sacc[nt][1]));
            mx1 = fmaxf(mx1, fmaxf(sacc[nt][2], sacc[nt][3]));
        }
        mx0 = fmaxf(mx0, __shfl_xor_sync(0xffffffffu, mx0, 1));
        mx0 = fmaxf(mx0, __shfl_xor_sync(0xffffffffu, mx0, 2));
        mx1 = fmaxf(mx1, __shfl_xor_sync(0xffffffffu, mx1, 1));
        mx1 = fmaxf(mx1, __shfl_xor_sync(0xffffffffu, mx1, 2));

        float mn0 = fmaxf(m0r, mx0);
        float mn1 = fmaxf(m1r, mx1);
        float corr0 = exp2f(m0r - mn0);
        float corr1 = exp2f(m1r - mn1);
        float sum0 = 0.0f, sum1 = 0.0f;
#pragma unroll
        for (int nt = 0; nt < 8; nt++) {
            float p0 = exp2f(sacc[nt][0] - mn0);
            float p1 = exp2f(sacc[nt][1] - mn0);
            float p2 = exp2f(sacc[nt][2] - mn1);
            float p3 = exp2f(sacc[nt][3] - mn1);
            sacc[nt][0] = p0; sacc[nt][1] = p1; sacc[nt][2] = p2; sacc[nt][3] = p3;
            sum0 += p0 + p1;
            sum1 += p2 + p3;
        }
        sum0 += __shfl_xor_sync(0xffffffffu, sum0, 1);
        sum0 += __shfl_xor_sync(0xffffffffu, sum0, 2);
        sum1 += __shfl_xor_sync(0xffffffffu, sum1, 1);
        sum1 += __shfl_xor_sync(0xffffffffu, sum1, 2);
        l0 = l0 * corr0 + sum0;
        l1 = l1 * corr1 + sum1;
        m0r = mn0; m1r = mn1;
#pragma unroll
        for (int nt = 0; nt < 8; nt++) {
            oacc[nt][0] *= corr0; oacc[nt][1] *= corr0;
            oacc[nt][2] *= corr1; oacc[nt][3] *= corr1;
        }

        // ---- stage P (tf32) into warp-private Ps rows, interleaved ----
        const int pc = ((2 * tig) & 3) * 2 + (tig >> 1);
#pragma unroll
        for (int nt = 0; nt < 8; nt++) {
            uint32_t* p0 = &Ps[(wid * 16 + g) * AP + nt * 8];
            p0[pc]     = f2tf(sacc[nt][0]);
            p0[pc + 2] = f2tf(sacc[nt][1]);
            uint32_t* p1 = &Ps[(wid * 16 + g + 8) * AP + nt * 8];
            p1[pc]     = f2tf(sacc[nt][2]);
            p1[pc + 2] = f2tf(sacc[nt][3]);
        }
        __syncwarp();

        // ---- O += P @ V ----
#pragma unroll
        for (int ks = 0; ks < 8; ks++) {
            int kk = ks * 8;
            uint2 a01 = *(const uint2*)&Ps[(wid * 16 + g)     * AP + kk + 2 * tig];
            uint2 a23 = *(const uint2*)&Ps[(wid * 16 + g + 8) * AP + kk + 2 * tig];
#pragma unroll
            for (int nt = 0; nt < 8; nt++) {
                uint32_t bf0 = Vs[(kk + tig)     * AP + nt * 8 + g];        // row swz = 0
                uint32_t bf1 = Vs[(kk + tig + 4) * AP + 4 + nt * 8 + g];    // row swz = 4
                mma8(oacc[nt], a01.x, a23.x, a01.y, a23.y, bf0, bf1);
            }
        }
        __syncwarp();
    }

    // ---- epilogue: normalize, tf32-round (feeds out-proj), write ----
    float inv0 = 1.0f / l0;
    float inv1 = 1.0f / l1;
    float* ob = out + ((size_t)b * Q_ + qrow_w) * D_ + h * HD_;
#pragma unroll
    for (int nt = 0; nt < 8; nt++) {
        int col = nt * 8 + 2 * tig;
        float2 v0 = make_float2(tfrnd(oacc[nt][0] * inv0), tfrnd(oacc[nt][1] * inv0));
        *(float2*)(ob + (size_t)g * D_ + col) = v0;
        float2 v1 = make_float2(tfrnd(oacc[nt][2] * inv1), tfrnd(oacc[nt][3] * inv1));
        *(float2*)(ob + (size_t)(g + 8) * D_ + col) = v1;
    }
}

// ---------------------------------------------------------------------------
// Launch
// ---------------------------------------------------------------------------
static const int GEMM_SMEM = 4 * GBUF * 4;   // 73728 B
static const int ATT_SMEM  = 5 * ABUF * 4;   // 92160 B

extern "C" void kernel_launch(void* const* d_in, const int* in_sizes, int n_in,
                              void* d_out, int out_size)
{
    const float* x  = (const float*)d_in[0];
    const float* Wq = (const float*)d_in[1];
    const float* bq = (const float*)d_in[2];
    const float* Wk = (const float*)d_in[3];
    const float* bk = (const float*)d_in[4];
    const float* Wv = (const float*)d_in[5];
    const float* bv = (const float*)d_in[6];
    const float* Wo = (const float*)d_in[7];
    const float* bo = (const float*)d_in[8];
    float* out = (float*)d_out;

    float *rx, *rwq, *rwk, *rwv, *rwo, *xq, *kk, *vv, *ao;
    cudaGetSymbolAddress((void**)&rx,  g_x);
    cudaGetSymbolAddress((void**)&rwq, g_wq);
    cudaGetSymbolAddress((void**)&rwk, g_wk);
    cudaGetSymbolAddress((void**)&rwv, g_wv);
    cudaGetSymbolAddress((void**)&rwo, g_wo);
    cudaGetSymbolAddress((void**)&xq,  g_xq);
    cudaGetSymbolAddress((void**)&kk,  g_k);
    cudaGetSymbolAddress((void**)&vv,  g_v);
    cudaGetSymbolAddress((void**)&ao,  g_ao);

    cudaFuncSetAttribute(gemm_tf32_cp,
                         cudaFuncAttributeMaxDynamicSharedMemorySize, GEMM_SMEM);
    cudaFuncSetAttribute(attn_cp_kernel,
                         cudaFuncAttributeMaxDynamicSharedMemorySize, ATT_SMEM);

    // Prepass: tf32-round x and weights
    round_kernel<<<(B_ * L_ * D_ / 4 + 255) / 256, 256>>>(x, rx, B_ * L_ * D_ / 4);
    round_w_kernel<<<dim3(D_ * D_ / 4 / 256, 4), 256>>>(Wq, rwq, Wk, rwk, Wv, rwv, Wo, rwo);

    // Fused QKV projections (rounded outputs)
    dim3 gqkv(D_ / 128, (B_ * L_) / 128, 3);
    gemm_tf32_cp<<<gqkv, 256, GEMM_SMEM>>>(rx,
                                           rwq, bq, xq,
                                           rwk, bk, kk,
                                           rwv, bv, vv, 1);

    // Flash attention (rounded output)
    attn_cp_kernel<<<dim3(Q_ / 64, H_, B_), 128, ATT_SMEM>>>(xq, kk, vv, ao);

    // Output projection (full-precision output)
    dim3 gout(D_ / 128, (B_ * Q_) / 128, 1);
    gemm_tf32_cp<<<gout, 256, GEMM_SMEM>>>(ao,
                                           rwo, bo, out,
                                           rwo, bo, out,
                                           rwo, bo, out, 0);
}

// round 7
// speedup vs baseline: 3.2949x; 1.0060x over previous
#include <cuda_runtime.h>
#include <cstdint>

// Problem constants
#define B_   2
#define L_   2048
#define Q_   4096
#define D_   512
#define H_   8
#define HD_  64

// ---------------------------------------------------------------------------
// Scratch (allocation-free: __device__ globals). All tensors that feed an MMA
// are stored as tf32-pre-rounded fp32 bit patterns, so cp.async can move them
// raw into smem and mma's truncation == round-to-nearest (numerics preserved).
// ---------------------------------------------------------------------------
__device__ float g_x [B_ * L_ * D_];   // tf32-rounded x
__device__ float g_wq[D_ * D_];
__device__ float g_wk[D_ * D_];
__device__ float g_wv[D_ * D_];
__device__ float g_wo[D_ * D_];
__device__ float g_xq[B_ * L_ * D_];   // x @ Wq^T + bq (rounded, pre-upsample)
__device__ float g_k [B_ * L_ * D_];
__device__ float g_v [B_ * L_ * D_];
__device__ float g_ao[B_ * Q_ * D_];   // attention output (rounded)

// ---------------------------------------------------------------------------
// Helpers
// ---------------------------------------------------------------------------
__device__ __forceinline__ uint32_t f2tf(float f) {
    uint32_t u;
    asm("cvt.rna.tf32.f32 %0, %1;" : "=r"(u) : "f"(f));
    return u;
}
__device__ __forceinline__ float tfrnd(float f) { return __uint_as_float(f2tf(f)); }

__device__ __forceinline__ void mma8(float* c,
                                     uint32_t a0, uint32_t a1, uint32_t a2, uint32_t a3,
                                     uint32_t b0, uint32_t b1) {
    asm volatile(
        "mma.sync.aligned.m16n8k8.row.col.f32.tf32.tf32.f32 "
        "{%0,%1,%2,%3}, {%4,%5,%6,%7}, {%8,%9}, {%0,%1,%2,%3};"
        : "+f"(c[0]), "+f"(c[1]), "+f"(c[2]), "+f"(c[3])
        : "r"(a0), "r"(a1), "r"(a2), "r"(a3), "r"(b0), "r"(b1));
}

__device__ __forceinline__ void cpasync16(uint32_t dst, const void* src) {
    asm volatile("cp.async.cg.shared.global [%0], [%1], 16;" :: "r"(dst), "l"(src));
}
__device__ __forceinline__ void cpcommit() { asm volatile("cp.async.commit_group;"); }
__device__ __forceinline__ void cpwait0()  { asm volatile("cp.async.wait_group 0;" ::: "memory"); }

// ---------------------------------------------------------------------------
// Prepass: tf32-round x and the four weight matrices into scratch.
// ---------------------------------------------------------------------------
__global__ void __launch_bounds__(256) round_kernel(
    const float* __restrict__ src, float* __restrict__ dst, int n4)
{
    int i = blockIdx.x * 256 + threadIdx.x;
    if (i < n4) {
        float4 v = ((const float4*)src)[i];
        v.x = tfrnd(v.x); v.y = tfrnd(v.y); v.z = tfrnd(v.z); v.w = tfrnd(v.w);
        ((float4*)dst)[i] = v;
    }
}

__global__ void __launch_bounds__(256) round_w_kernel(
    const float* __restrict__ w0, float* __restrict__ d0,
    const float* __restrict__ w1, float* __restrict__ d1,
    const float* __restrict__ w2, float* __restrict__ d2,
    const float* __restrict__ w3, float* __restrict__ d3)
{
    const float* s = w0; float* d = d0;
    if (blockIdx.y == 1) { s = w1; d = d1; }
    else if (blockIdx.y == 2) { s = w2; d = d2; }
    else if (blockIdx.y == 3) { s = w3; d = d3; }
    int i = blockIdx.x * 256 + threadIdx.x;   // 65536 float4 per W
    float4 v = ((const float4*)s)[i];
    v.x = tfrnd(v.x); v.y = tfrnd(v.y); v.z = tfrnd(v.z); v.w = tfrnd(v.w);
    ((float4*)d)[i] = v;
}

// ---------------------------------------------------------------------------
// tf32 GEMM with cp.async 2-stage pipeline. C = A @ W^T + bias. K = N = 512.
// Block 128x128, k-chunk 32 (x2 buffers). 256 threads = 8 warps (2m x 4n).
// ---------------------------------------------------------------------------
#define GST 36
#define GBUF (128 * GST)

__global__ void __launch_bounds__(256, 2) gemm_tf32_cp(
    const float* __restrict__ A,
    const float* __restrict__ W0, const float* __restrict__ b0_, float* __restrict__ C0,
    const float* __restrict__ W1, const float* __restrict__ b1_, float* __restrict__ C1,
    const float* __restrict__ W2, const float* __restrict__ b2_, float* __restrict__ C2,
    int roundOut)
{
    const float* W = W0; const float* bias = b0_; float* C = C0;
    if (blockIdx.z == 1) { W = W1; bias = b1_; C = C1; }
    else if (blockIdx.z == 2) { W = W2; bias = b2_; C = C2; }

    extern __shared__ uint32_t gsm[];   // [Abuf0][Abuf1][Wbuf0][Wbuf1]
    const uint32_t sbase = (uint32_t)__cvta_generic_to_shared(gsm);

    const int t    = threadIdx.x;
    const int lane = t & 31;
    const int wid  = t >> 5;
    const int g    = lane >> 2;
    const int tig  = lane & 3;
    const int wm   = (wid & 1) * 64;
    const int wn   = (wid >> 1) * 32;

    const int m0 = blockIdx.y * 128;
    const int n0 = blockIdx.x * 128;

    const int fr0 = t >> 3;
    const int fc  = (t & 7) * 4;
    const float* Asrc = A + (size_t)(m0 + fr0) * D_ + fc;
    const float* Wsrc = W + (size_t)(n0 + fr0) * D_ + fc;
    const uint32_t dW = fr0 * GST + fc;

    float acc[4][4][4];
#pragma unroll
    for (int mt = 0; mt < 4; mt++)
#pragma unroll
        for (int nt = 0; nt < 4; nt++)
#pragma unroll
            for (int c = 0; c < 4; c++) acc[mt][nt][c] = 0.0f;

#pragma unroll
    for (int i = 0; i < 4; i++) {
        cpasync16(sbase + (dW + i * 32 * GST) * 4,            Asrc + (size_t)i * 32 * D_);
        cpasync16(sbase + (2 * GBUF + dW + i * 32 * GST) * 4, Wsrc + (size_t)i * 32 * D_);
    }
    cpcommit();

    for (int ic = 0; ic < 16; ic++) {
        cpwait0();
        __syncthreads();
        if (ic < 15) {
            const int bf = (ic + 1) & 1;
            const size_t ko = (size_t)(ic + 1) * 32;
#pragma unroll
            for (int i = 0; i < 4; i++) {
                cpasync16(sbase + (bf * GBUF + dW + i * 32 * GST) * 4,
                          Asrc + (size_t)i * 32 * D_ + ko);
                cpasync16(sbase + ((2 + bf) * GBUF + dW + i * 32 * GST) * 4,
                          Wsrc + (size_t)i * 32 * D_ + ko);
            }
            cpcommit();
        }
        const uint32_t* As = gsm + (ic & 1) * GBUF;
        const uint32_t* Ws = gsm + (2 + (ic & 1)) * GBUF;

#pragma unroll
        for (int ks = 0; ks < 32; ks += 8) {
            uint32_t af[4][4];
#pragma unroll
            for (int mt = 0; mt < 4; mt++) {
                int r = wm + mt * 16;
                af[mt][0] = As[(r + g)     * GST + ks + tig];
                af[mt][1] = As[(r + g + 8) * GST + ks + tig];
                af[mt][2] = As[(r + g)     * GST + ks + tig + 4];
                af[mt][3] = As[(r + g + 8) * GST + ks + tig + 4];
            }
#pragma unroll
            for (int nt = 0; nt < 4; nt++) {
                int n = wn + nt * 8;
                uint32_t bf0 = Ws[(n + g) * GST + ks + tig];
                uint32_t bf1 = Ws[(n + g) * GST + ks + tig + 4];
#pragma unroll
                for (int mt = 0; mt < 4; mt++)
                    mma8(acc[mt][nt], af[mt][0], af[mt][1], af[mt][2], af[mt][3], bf0, bf1);
            }
        }
    }

#pragma unroll
    for (int nt = 0; nt < 4; nt++) {
        int col = n0 + wn + nt * 8 + 2 * tig;
        float2 bi = *(const float2*)(bias + col);
#pragma unroll
        for (int mt = 0; mt < 4; mt++) {
            int r = m0 + wm + mt * 16 + g;
            float2 v0 = make_float2(acc[mt][nt][0] + bi.x, acc[mt][nt][1] + bi.y);
            float2 v1 = make_float2(acc[mt][nt][2] + bi.x, acc[mt][nt][3] + bi.y);
            if (roundOut) {
                v0.x = tfrnd(v0.x); v0.y = tfrnd(v0.y);
                v1.x = tfrnd(v1.x); v1.y = tfrnd(v1.y);
            }
            *(float2*)(C + (size_t)r * D_ + col)       = v0;
            *(float2*)(C + (size_t)(r + 8) * D_ + col) = v1;
        }
    }
}

// ---------------------------------------------------------------------------
// Flash attention: tf32 mma, fused upsample, cp.async double-buffered K/V,
// register-resident Q fragments, exp2 softmax, reversed causal schedule.
// NO separate P buffer: P is staged into the CURRENT-parity K buffer, which is
// dead after S=QK^T (the tile+1 prefetch targets the opposite parity, and the
// tile+2 prefetch into this buffer is only issued after the next top-of-loop
// barrier). A __syncthreads between QK-reads and P-writes makes it race-free.
// Q stages through Kbuf1 pre-loop (consumed into registers before the tile-1
// prefetch can be issued). Smem = 4 buffers = 72 KB -> 3 CTAs/SM.
// ---------------------------------------------------------------------------
#define AP 72
#define ABUF (64 * AP)

__global__ void __launch_bounds__(128, 3) attn_cp_kernel(
    const float* __restrict__ xq, const float* __restrict__ k,
    const float* __restrict__ v, float* __restrict__ out)
{
    extern __shared__ uint32_t sm[];   // [Kbuf0][Kbuf1][Vbuf0][Vbuf1]
    const uint32_t sbase = (uint32_t)__cvta_generic_to_shared(sm);

    const int t    = threadIdx.x;
    const int lane = t & 31;
    const int wid  = t >> 5;
    const int g    = lane >> 2;
    const int tig  = lane & 3;

    const int bx = gridDim.x - 1 - blockIdx.x;   // reversed schedule
    const int q0 = bx * 64;
    const int h  = blockIdx.y;
    const int b  = blockIdx.z;

    // 512^-0.5 * log2(e): softmax in exp2 domain
    const float scale = 0.04419417382415922f * 1.44269504088896340f;

    const float* xqb = xq + (size_t)b * L_ * D_ + h * HD_;
    const float* kb  = k  + (size_t)b * L_ * D_ + h * HD_;
    const float* vb  = v  + (size_t)b * L_ * D_ + h * HD_;

    const int kr0 = t >> 4;          // base row (+8 per i)
    const int kc4 = (t & 15) * 4;

    // ---- prologue: tile 0 -> Kbuf0 / Vbuf0 ----
#pragma unroll
    for (int i = 0; i < 8; i++) {
        int row = kr0 + i * 8;
        uint32_t d = (row * AP + ((row >> 2) & 1) * 4 + kc4) * 4;
        cpasync16(sbase + d,                kb + (size_t)row * D_ + kc4);
        cpasync16(sbase + 2 * ABUF * 4 + d, vb + (size_t)row * D_ + kc4);
    }
    cpcommit();

    // ---- Q staging into Kbuf1: fused upsample + scale + tf32, interleaved ----
    uint32_t* Qstage = sm + ABUF;
#pragma unroll
    for (int i = 0; i < 8; i++) {
        int f    = i * 128 + t;
        int row  = f >> 4;
        int c4   = (f & 15) * 4;
        int qrow = q0 + row;
        float4 val;
        if (qrow == 0) {
            val = *(const float4*)(xqb + c4);
        } else {
            float src = (qrow - 0.5f) * 0.5f;
            int i0 = (int)src;
            float w = src - (float)i0;
            int i1 = min(i0 + 1, L_ - 1);
            float4 a = *(const float4*)(xqb + (size_t)i0 * D_ + c4);
            float4 c = *(const float4*)(xqb + (size_t)i1 * D_ + c4);
            val.x = a.x + (c.x - a.x) * w;
            val.y = a.y + (c.y - a.y) * w;
            val.z = a.z + (c.z - a.z) * w;
            val.w = a.w + (c.w - a.w) * w;
        }
        int oct = c4 >> 3;
        int par = (c4 >> 2) & 1;
        uint32_t* dst = &Qstage[row * AP + oct * 8 + par];
        dst[0] = f2tf(val.x * scale);
        dst[2] = f2tf(val.y * scale);
        dst[4] = f2tf(val.z * scale);
        dst[6] = f2tf(val.w * scale);
    }
    __syncthreads();

    // ---- Q fragments to registers (Kbuf1 free afterwards) ----
    uint32_t qf[8][4];
#pragma unroll
    for (int ks = 0; ks < 8; ks++) {
        int kk = ks * 8;
        uint2 a01 = *(const uint2*)&Qstage[(wid * 16 + g)     * AP + kk + 2 * tig];
        uint2 a23 = *(const uint2*)&Qstage[(wid * 16 + g + 8) * AP + kk + 2 * tig];
        qf[ks][0] = a01.x; qf[ks][1] = a23.x; qf[ks][2] = a01.y; qf[ks][3] = a23.y;
    }

    float m0r = -1e30f, m1r = -1e30f, l0 = 0.0f, l1 = 0.0f;
    float oacc[8][4];
#pragma unroll
    for (int nt = 0; nt < 8; nt++)
#pragma unroll
        for (int c = 0; c < 4; c++) oacc[nt][c] = 0.0f;

    const int ntiles = min(bx + 1, L_ / 64);
    const int qrow_w = q0 + wid * 16;
    const int gsw    = ((g >> 2) & 1) * 4;   // row-swizzle shift for K B-frags

    for (int tile = 0; tile < ntiles; tile++) {
        const int k0 = tile * 64;
        cpwait0();
        __syncthreads();   // data visible; all warps done with prev P/V + Q regs

        if (tile + 1 < ntiles) {
            const int bf = (tile + 1) & 1;
            const size_t ko = (size_t)(k0 + 64) * D_;
#pragma unroll
            for (int i = 0; i < 8; i++) {
                int row = kr0 + i * 8;
                uint32_t d = (row * AP + ((row >> 2) & 1) * 4 + kc4) * 4;
                cpasync16(sbase + bf * ABUF * 4 + d,       kb + ko + (size_t)row * D_ + kc4);
                cpasync16(sbase + (2 + bf) * ABUF * 4 + d, vb + ko + (size_t)row * D_ + kc4);
            }
            cpcommit();
        }

        const uint32_t* Ks = sm + (tile & 1) * ABUF;
        const uint32_t* Vs = sm + (2 + (tile & 1)) * ABUF;

        // ---- S = Q @ K^T (16x64 per warp) ----
        float sacc[8][4];
#pragma unroll
        for (int nt = 0; nt < 8; nt++)
#pragma unroll
            for (int c = 0; c < 4; c++) sacc[nt][c] = 0.0f;

#pragma unroll
        for (int ks = 0; ks < 8; ks++) {
            int kk = ks * 8;
#pragma unroll
            for (int nt = 0; nt < 8; nt++) {
                const uint32_t* kr = &Ks[(nt * 8 + g) * AP + gsw + kk + tig];
                mma8(sacc[nt], qf[ks][0], qf[ks][1], qf[ks][2], qf[ks][3], kr[0], kr[4]);
            }
        }

        // ---- causal mask (diagonal tile only) ----
        if (k0 == q0) {
            int r0 = qrow_w + g;
            int r1 = r0 + 8;
#pragma unroll
            for (int nt = 0; nt < 8; nt++) {
                int col = k0 + nt * 8 + 2 * tig;
                if (col     > r0) sacc[nt][0] = -1e30f;
                if (col + 1 > r0) sacc[nt][1] = -1e30f;
                if (col     > r1) sacc[nt][2] = -1e30f;
                if (col + 1 > r1) sacc[nt][3] = -1e30f;
            }
        }

        // ---- online softmax (exp2 domain) ----
        float mx0 = -1e30f, mx1 = -1e30f;
#pragma unroll
        for (int nt = 0; nt < 8; nt++) {
            mx0 = fmaxf(mx0, fmaxf(sacc[nt][0], sacc[nt][1]));
            mx1 = fmaxf(mx1, fmaxf(sacc[nt][2], sacc[nt][3]));
        }
        mx0 = fmaxf(mx0, __shfl_xor_sync(0xffffffffu, mx0, 1));
        mx0 = fmaxf(mx0, __shfl_xor_sync(0xffffffffu, mx0, 2));
        mx1 = fmaxf(mx1, __shfl_xor_sync(0xffffffffu, mx1, 1));
        mx1 = fmaxf(mx1, __shfl_xor_sync(0xffffffffu, mx1, 2));

        float mn0 = fmaxf(m0r, mx0);
        float mn1 = fmaxf(m1r, mx1);
        float corr0 = exp2f(m0r - mn0);
        float corr1 = exp2f(m1r - mn1);
        float sum0 = 0.0f, sum1 = 0.0f;
#pragma unroll
        for (int nt = 0; nt < 8; nt++) {
            float p0 = exp2f(sacc[nt][0] - mn0);
            float p1 = exp2f(sacc[nt][1] - mn0);
            float p2 = exp2f(sacc[nt][2] - mn1);
            float p3 = exp2f(sacc[nt][3] - mn1);
            sacc[nt][0] = p0; sacc[nt][1] = p1; sacc[nt][2] = p2; sacc[nt][3] = p3;
            sum0 += p0 + p1;
            sum1 += p2 + p3;
        }
        sum0 += __shfl_xor_sync(0xffffffffu, sum0, 1);
        sum0 += __shfl_xor_sync(0xffffffffu, sum0, 2);
        sum1 += __shfl_xor_sync(0xffffffffu, sum1, 1);
        sum1 += __shfl_xor_sync(0xffffffffu, sum1, 2);
        l0 = l0 * corr0 + sum0;
        l1 = l1 * corr1 + sum1;
        m0r = mn0; m1r = mn1;
#pragma unroll
        for (int nt = 0; nt < 8; nt++) {
            oacc[nt][0] *= corr0; oacc[nt][1] *= corr0;
            oacc[nt][2] *= corr1; oacc[nt][3] *= corr1;
        }

        // ---- all warps done reading Ks -> reuse it as the P buffer ----
        __syncthreads();
        uint32_t* Ps = sm + (tile & 1) * ABUF;

        const int pc = ((2 * tig) & 3) * 2 + (tig >> 1);
#pragma unroll
        for (int nt = 0; nt < 8; nt++) {
            uint32_t* p0 = &Ps[(wid * 16 + g) * AP + nt * 8];
            p0[pc]     = f2tf(sacc[nt][0]);
            p0[pc + 2] = f2tf(sacc[nt][1]);
            uint32_t* p1 = &Ps[(wid * 16 + g + 8) * AP + nt * 8];
            p1[pc]     = f2tf(sacc[nt][2]);
            p1[pc + 2] = f2tf(sacc[nt][3]);
        }
        __syncwarp();

        // ---- O += P @ V ----
#pragma unroll
        for (int ks = 0; ks < 8; ks++) {
            int kk = ks * 8;
            uint2 a01 = *(const uint2*)&Ps[(wid * 16 + g)     * AP + kk + 2 * tig];
            uint2 a23 = *(const uint2*)&Ps[(wid * 16 + g + 8) * AP + kk + 2 * tig];
#pragma unroll
            for (int nt = 0; nt < 8; nt++) {
                uint32_t bf0 = Vs[(kk + tig)     * AP + nt * 8 + g];        // row swz = 0
                uint32_t bf1 = Vs[(kk + tig + 4) * AP + 4 + nt * 8 + g];    // row swz = 4
                mma8(oacc[nt], a01.x, a23.x, a01.y, a23.y, bf0, bf1);
            }
        }
    }

    // ---- epilogue: normalize, tf32-round (feeds out-proj), write ----
    float inv0 = 1.0f / l0;
    float inv1 = 1.0f / l1;
    float* ob = out + ((size_t)b * Q_ + qrow_w) * D_ + h * HD_;
#pragma unroll
    for (int nt = 0; nt < 8; nt++) {
        int col = nt * 8 + 2 * tig;
        float2 v0 = make_float2(tfrnd(oacc[nt][0] * inv0), tfrnd(oacc[nt][1] * inv0));
        *(float2*)(ob + (size_t)g * D_ + col) = v0;
        float2 v1 = make_float2(tfrnd(oacc[nt][2] * inv1), tfrnd(oacc[nt][3] * inv1));
        *(float2*)(ob + (size_t)(g + 8) * D_ + col) = v1;
    }
}

// ---------------------------------------------------------------------------
// Launch
// ---------------------------------------------------------------------------
static const int GEMM_SMEM = 4 * GBUF * 4;   // 73728 B
static const int ATT_SMEM  = 4 * ABUF * 4;   // 73728 B -> 3 CTAs/SM

extern "C" void kernel_launch(void* const* d_in, const int* in_sizes, int n_in,
                              void* d_out, int out_size)
{
    const float* x  = (const float*)d_in[0];
    const float* Wq = (const float*)d_in[1];
    const float* bq = (const float*)d_in[2];
    const float* Wk = (const float*)d_in[3];
    const float* bk = (const float*)d_in[4];
    const float* Wv = (const float*)d_in[5];
    const float* bv = (const float*)d_in[6];
    const float* Wo = (const float*)d_in[7];
    const float* bo = (const float*)d_in[8];
    float* out = (float*)d_out;

    float *rx, *rwq, *rwk, *rwv, *rwo, *xq, *kk, *vv, *ao;
    cudaGetSymbolAddress((void**)&rx,  g_x);
    cudaGetSymbolAddress((void**)&rwq, g_wq);
    cudaGetSymbolAddress((void**)&rwk, g_wk);
    cudaGetSymbolAddress((void**)&rwv, g_wv);
    cudaGetSymbolAddress((void**)&rwo, g_wo);
    cudaGetSymbolAddress((void**)&xq,  g_xq);
    cudaGetSymbolAddress((void**)&kk,  g_k);
    cudaGetSymbolAddress((void**)&vv,  g_v);
    cudaGetSymbolAddress((void**)&ao,  g_ao);

    cudaFuncSetAttribute(gemm_tf32_cp,
                         cudaFuncAttributeMaxDynamicSharedMemorySize, GEMM_SMEM);
    cudaFuncSetAttribute(attn_cp_kernel,
                         cudaFuncAttributeMaxDynamicSharedMemorySize, ATT_SMEM);

    // Prepass: tf32-round x and weights
    round_kernel<<<(B_ * L_ * D_ / 4 + 255) / 256, 256>>>(x, rx, B_ * L_ * D_ / 4);
    round_w_kernel<<<dim3(D_ * D_ / 4 / 256, 4), 256>>>(Wq, rwq, Wk, rwk, Wv, rwv, Wo, rwo);

    // Fused QKV projections (rounded outputs)
    dim3 gqkv(D_ / 128, (B_ * L_) / 128, 3);
    gemm_tf32_cp<<<gqkv, 256, GEMM_SMEM>>>(rx,
                                           rwq, bq, xq,
                                           rwk, bk, kk,
                                           rwv, bv, vv, 1);

    // Flash attention (rounded output)
    attn_cp_kernel<<<dim3(Q_ / 64, H_, B_), 128, ATT_SMEM>>>(xq, kk, vv, ao);

    // Output projection (full-precision output)
    dim3 gout(D_ / 128, (B_ * Q_) / 128, 1);
    gemm_tf32_cp<<<gout, 256, GEMM_SMEM>>>(ao,
                                           rwo, bo, out,
                                           rwo, bo, out,
                                           rwo, bo, out, 0);
}